// round 5
// baseline (speedup 1.0000x reference)
#include <cuda_runtime.h>
#include <cuda_bf16.h>
#include <stdint.h>
#include <math.h>

// Problem constants
#define BATCH 4
#define SEQ   2048
#define DIM   1024
#define MTOT  (BATCH * SEQ)      // 8192
#define BETA  0.03125f

// GEMM tiling: 128x128 CTA tile, K-chunk 64 bf16 (128B rows, SW128 swizzle)
#define KC       64
#define TB       16384               // one tile: 128 rows * 128 B
#define STAGE_B  (4 * TB)            // Ah | Al | Bh | Bl = 64 KB
#define SMEM_TOTAL (2 * STAGE_B)     // 128 KB (2 stages)

// ---------------------------------------------------------------------------
// Scratch (__device__ globals; allocation-free rule)
// ---------------------------------------------------------------------------
__device__ __align__(16) __nv_bfloat16 g_xh[3 * MTOT * DIM], g_xl[3 * MTOT * DIM];
__device__ __align__(16) __nv_bfloat16 g_wh[3 * DIM * DIM],  g_wl[3 * DIM * DIM];
__device__ __align__(16) float         g_bias[3 * DIM];
__device__ __align__(16) __nv_bfloat16 g_qkvh[3 * MTOT * DIM], g_qkvl[3 * MTOT * DIM];
__device__ __align__(16) __nv_bfloat16 g_vth[MTOT * DIM], g_vtl[MTOT * DIM];
__device__ __align__(16) float         g_sf[(size_t)BATCH * SEQ * SEQ];
__device__ __align__(16) __nv_bfloat16 g_ah[(size_t)BATCH * SEQ * SEQ];
__device__ __align__(16) __nv_bfloat16 g_al[(size_t)BATCH * SEQ * SEQ];

// ---------------------------------------------------------------------------
// Helpers
// ---------------------------------------------------------------------------
__device__ __forceinline__ uint32_t s2u(const void* p) {
    return (uint32_t)__cvta_generic_to_shared(p);
}
__device__ __forceinline__ void cp16(uint32_t s, const void* g) {
    asm volatile("cp.async.cg.shared.global [%0], [%1], 16;" :: "r"(s), "l"(g));
}
__device__ __forceinline__ void bf_split2(float a, float b,
                                          __nv_bfloat162& hh, __nv_bfloat162& ll) {
    __nv_bfloat16 ha = __float2bfloat16(a), hb = __float2bfloat16(b);
    hh.x = ha; hh.y = hb;
    ll.x = __float2bfloat16(a - __bfloat162float(ha));
    ll.y = __float2bfloat16(b - __bfloat162float(hb));
}

#define LDSM4(r, addr)                                                        \
    asm volatile("ldmatrix.sync.aligned.m8n8.x4.shared.b16 {%0,%1,%2,%3}, [%4];" \
                 : "=r"((r)[0]), "=r"((r)[1]), "=r"((r)[2]), "=r"((r)[3])     \
                 : "r"(addr))

#define MMA_BF16(d, a, b)                                                     \
    asm volatile(                                                             \
        "mma.sync.aligned.m16n8k16.row.col.f32.bf16.bf16.f32 "                \
        "{%0,%1,%2,%3}, {%4,%5,%6,%7}, {%8,%9}, {%0,%1,%2,%3};\n"             \
        : "+f"((d)[0]), "+f"((d)[1]), "+f"((d)[2]), "+f"((d)[3])              \
        : "r"((a)[0]), "r"((a)[1]), "r"((a)[2]), "r"((a)[3]),                 \
          "r"((b)[0]), "r"((b)[1]))

// ---------------------------------------------------------------------------
// GEMM: C[M,N] = A[M,K] @ B[N,K]^T (+bias), bf16 hi/lo 3-pass, fp32 accum.
// A: m x k row-major (k contig), B: n x k row-major. Grid (N/128, M/128, z).
// EPI: 0 = fp32, 2 = bf16 hi/lo split + bias
// ---------------------------------------------------------------------------
template <int EPI>
__global__ void __launch_bounds__(256) gemm_ld(
    const __nv_bfloat16* __restrict__ Ahi, const __nv_bfloat16* __restrict__ Alo, long sA,
    const __nv_bfloat16* __restrict__ Bhi, const __nv_bfloat16* __restrict__ Blo, long sB,
    const float* __restrict__ bias, int biasStride,
    float* __restrict__ C, __nv_bfloat16* __restrict__ Chi,
    __nv_bfloat16* __restrict__ Clo, long sC,
    int K, int ldc)
{
    extern __shared__ __align__(1024) char smem[];
    const uint32_t sb0 = s2u(smem);

    const int t = threadIdx.x;
    const int lane = t & 31;
    const int warp = t >> 5;
    const int wm = warp >> 2;            // 0..1 -> 64 rows
    const int wn = warp & 3;             // 0..3 -> 32 cols
    const int bz = blockIdx.z;

    const size_t aBase = (size_t)bz * sA + (size_t)blockIdx.y * 128 * K;
    const size_t bBase = (size_t)bz * sB + (size_t)blockIdx.x * 128 * K;

    // ldmatrix lane constants (x4: lanes l -> matrix l/8, row l%8)
    const int m4 = lane >> 3;
    const int rA = ((m4 & 1) << 3) + (lane & 7);   // A: m0=(r,k0) m1=(r+8,k0) m2=(r,k+8) m3=(r+8,k+8)
    const int kA = (m4 >> 1) << 4;
    const int rB = ((m4 >> 1) << 3) + (lane & 7);  // B: m0=(n,k0) m1=(n,k+8) m2=(n+8,k0) m3=(n+8,k+8)
    const int kB = (m4 & 1) << 4;

    auto load_stage = [&](int st, int k0) {
        const uint32_t so = sb0 + st * STAGE_B;
#pragma unroll
        for (int i = 0; i < 4; i++) {
            int c = t * 4 + i;               // 1024 16B-chunks per tile
            int row = c >> 3;
            int col = c & 7;
            uint32_t sw = row * 128 + ((col * 16) ^ ((row & 7) << 4));
            size_t ga = aBase + (size_t)row * K + k0 + col * 8;
            size_t gb = bBase + (size_t)row * K + k0 + col * 8;
            cp16(so + sw,          Ahi + ga);
            cp16(so + TB + sw,     Alo + ga);
            cp16(so + 2 * TB + sw, Bhi + gb);
            cp16(so + 3 * TB + sw, Blo + gb);
        }
        asm volatile("cp.async.commit_group;" ::: "memory");
    };

    float acc[4][4][4] = {};
    const int nk = K / KC;
    load_stage(0, 0);

    for (int kt = 0; kt < nk; kt++) {
        if (kt + 1 < nk) {
            load_stage((kt + 1) & 1, (kt + 1) * KC);
            asm volatile("cp.async.wait_group 1;" ::: "memory");
        } else {
            asm volatile("cp.async.wait_group 0;" ::: "memory");
        }
        __syncthreads();

        const uint32_t st = sb0 + (kt & 1) * STAGE_B;
#pragma unroll
        for (int s = 0; s < 4; s++) {            // 4 x k16 per chunk
            const int kb = s * 32;               // byte offset in 128B row
            uint32_t ah[4][4], al[4][4], bh[2][4], bl[2][4];
#pragma unroll
            for (int mi = 0; mi < 4; mi++) {
                int row = wm * 64 + mi * 16 + rA;
                uint32_t ad = st + row * 128 + ((kb + kA) ^ ((row & 7) << 4));
                LDSM4(ah[mi], ad);
                LDSM4(al[mi], ad + TB);
            }
#pragma unroll
            for (int nt = 0; nt < 2; nt++) {
                int row = wn * 32 + nt * 16 + rB;
                uint32_t ad = st + 2 * TB + row * 128 + ((kb + kB) ^ ((row & 7) << 4));
                LDSM4(bh[nt], ad);
                LDSM4(bl[nt], ad + TB);
            }
#pragma unroll
            for (int mi = 0; mi < 4; mi++)
#pragma unroll
                for (int ni = 0; ni < 4; ni++) {
                    const uint32_t* bph = &bh[ni >> 1][(ni & 1) * 2];
                    const uint32_t* bpl = &bl[ni >> 1][(ni & 1) * 2];
                    MMA_BF16(acc[mi][ni], ah[mi], bph);
                    MMA_BF16(acc[mi][ni], ah[mi], bpl);
                    MMA_BF16(acc[mi][ni], al[mi], bph);
                }
        }
        __syncthreads();
    }

    // Epilogue
    const int r = lane >> 2;
    const int cq = lane & 3;
    const int row0 = blockIdx.y * 128 + wm * 64;
    const int col0 = blockIdx.x * 128 + wn * 32;
    const size_t zC = (size_t)bz * sC;

#pragma unroll
    for (int mi = 0; mi < 4; mi++) {
#pragma unroll
        for (int ni = 0; ni < 4; ni++) {
            int rr = row0 + mi * 16 + r;
            int cc = col0 + ni * 8 + 2 * cq;
            if (EPI == 2) {
                float b0 = bias[bz * biasStride + cc];
                float b1 = bias[bz * biasStride + cc + 1];
                __nv_bfloat162 hh, ll;
                bf_split2(acc[mi][ni][0] + b0, acc[mi][ni][1] + b1, hh, ll);
                *(__nv_bfloat162*)(Chi + zC + (size_t)rr * ldc + cc) = hh;
                *(__nv_bfloat162*)(Clo + zC + (size_t)rr * ldc + cc) = ll;
                bf_split2(acc[mi][ni][2] + b0, acc[mi][ni][3] + b1, hh, ll);
                *(__nv_bfloat162*)(Chi + zC + (size_t)(rr + 8) * ldc + cc) = hh;
                *(__nv_bfloat162*)(Clo + zC + (size_t)(rr + 8) * ldc + cc) = ll;
            } else {
                float* Cp = C + zC;
                float2 v0 = make_float2(acc[mi][ni][0], acc[mi][ni][1]);
                float2 v1 = make_float2(acc[mi][ni][2], acc[mi][ni][3]);
                *(float2*)(Cp + (size_t)rr * ldc + cc) = v0;
                *(float2*)(Cp + (size_t)(rr + 8) * ldc + cc) = v1;
            }
        }
    }
}

// ---------------------------------------------------------------------------
// Batched elementwise split: 3 fp32 sources -> hi/lo bf16 (z picks source)
// ---------------------------------------------------------------------------
__global__ void __launch_bounds__(256) split3(
    const float* __restrict__ s0, const float* __restrict__ s1,
    const float* __restrict__ s2, __nv_bfloat16* __restrict__ hi,
    __nv_bfloat16* __restrict__ lo, int n4each)
{
    const int z = blockIdx.z;
    const float* x = (z == 0) ? s0 : (z == 1) ? s1 : s2;
    int i = blockIdx.x * 256 + threadIdx.x;
    if (i >= n4each) return;
    float4 v = ((const float4*)x)[i];
    __nv_bfloat162 h0, l0, h1, l1;
    bf_split2(v.x, v.y, h0, l0);
    bf_split2(v.z, v.w, h1, l1);
    size_t base = (size_t)z * n4each * 2;   // in bf162 units: n4each*4/2
    ((__nv_bfloat162*)hi)[base + 2 * i]     = h0;
    ((__nv_bfloat162*)hi)[base + 2 * i + 1] = h1;
    ((__nv_bfloat162*)lo)[base + 2 * i]     = l0;
    ((__nv_bfloat162*)lo)[base + 2 * i + 1] = l1;
}

// ---------------------------------------------------------------------------
// Batched split + transpose: W_z[R][C] fp32 -> hi/lo[z][C][R] bf16
// grid (C/32, R/32, 3), block (32,8)
// ---------------------------------------------------------------------------
__global__ void __launch_bounds__(256) wsplitT3(
    const float* __restrict__ s0, const float* __restrict__ s1,
    const float* __restrict__ s2, __nv_bfloat16* __restrict__ hi,
    __nv_bfloat16* __restrict__ lo, int R, int Ccols)
{
    __shared__ float tile[32][33];
    const int z = blockIdx.z;
    const float* xp = (z == 0) ? s0 : (z == 1) ? s1 : s2;
    const size_t zo = (size_t)z * R * Ccols;
    const int c0 = blockIdx.x * 32, r0 = blockIdx.y * 32;
    const int tx = threadIdx.x, ty = threadIdx.y;
#pragma unroll
    for (int i = 0; i < 32; i += 8)
        tile[ty + i][tx] = xp[(size_t)(r0 + ty + i) * Ccols + c0 + tx];
    __syncthreads();
#pragma unroll
    for (int i = 0; i < 32; i += 8) {
        float v = tile[tx][ty + i];
        __nv_bfloat16 h = __float2bfloat16(v);
        __nv_bfloat16 l = __float2bfloat16(v - __bfloat162float(h));
        size_t o = zo + (size_t)(c0 + ty + i) * R + r0 + tx;
        hi[o] = h;
        lo[o] = l;
    }
}

// ---------------------------------------------------------------------------
// bf16 hi+lo transpose: v[z][S][D] -> vt[z][D][S]. grid (D/32, S/32, BATCH)
// ---------------------------------------------------------------------------
__global__ void __launch_bounds__(256) vtransT(
    const __nv_bfloat16* __restrict__ vh, const __nv_bfloat16* __restrict__ vl,
    __nv_bfloat16* __restrict__ vth, __nv_bfloat16* __restrict__ vtl)
{
    __shared__ __nv_bfloat16 th[32][33], tl[32][33];
    const int z = blockIdx.z;
    const int c0 = blockIdx.x * 32, r0 = blockIdx.y * 32;
    const int tx = threadIdx.x, ty = threadIdx.y;
    const size_t inz = (size_t)z * SEQ * DIM;
#pragma unroll
    for (int i = 0; i < 32; i += 8) {
        size_t o = inz + (size_t)(r0 + ty + i) * DIM + c0 + tx;
        th[ty + i][tx] = vh[o];
        tl[ty + i][tx] = vl[o];
    }
    __syncthreads();
#pragma unroll
    for (int i = 0; i < 32; i += 8) {
        size_t o = inz + (size_t)(c0 + ty + i) * SEQ + r0 + tx;
        vth[o] = th[tx][ty + i];
        vtl[o] = tl[tx][ty + i];
    }
}

// ---------------------------------------------------------------------------
// Row softmax (BETA folded) fused with bf16 hi/lo split output
// ---------------------------------------------------------------------------
__global__ void __launch_bounds__(256) softmax_split(
    const float* __restrict__ S, __nv_bfloat16* __restrict__ Ah,
    __nv_bfloat16* __restrict__ Al)
{
    __shared__ float red[256];
    const int t = threadIdx.x;
    const size_t base = (size_t)blockIdx.x * SEQ;
    const float* p = S + base;

    float4 v0 = *(const float4*)(p + t * 4);
    float4 v1 = *(const float4*)(p + 1024 + t * 4);
    v0.x *= BETA; v0.y *= BETA; v0.z *= BETA; v0.w *= BETA;
    v1.x *= BETA; v1.y *= BETA; v1.z *= BETA; v1.w *= BETA;

    float m = fmaxf(fmaxf(fmaxf(v0.x, v0.y), fmaxf(v0.z, v0.w)),
                    fmaxf(fmaxf(v1.x, v1.y), fmaxf(v1.z, v1.w)));
    red[t] = m;
    __syncthreads();
    for (int s = 128; s > 0; s >>= 1) {
        if (t < s) red[t] = fmaxf(red[t], red[t + s]);
        __syncthreads();
    }
    m = red[0];
    __syncthreads();

    v0.x = __expf(v0.x - m); v0.y = __expf(v0.y - m);
    v0.z = __expf(v0.z - m); v0.w = __expf(v0.w - m);
    v1.x = __expf(v1.x - m); v1.y = __expf(v1.y - m);
    v1.z = __expf(v1.z - m); v1.w = __expf(v1.w - m);

    float sum = (v0.x + v0.y) + (v0.z + v0.w) + (v1.x + v1.y) + (v1.z + v1.w);
    red[t] = sum;
    __syncthreads();
    for (int s = 128; s > 0; s >>= 1) {
        if (t < s) red[t] += red[t + s];
        __syncthreads();
    }
    const float inv = 1.0f / red[0];

    float vv[8] = { v0.x * inv, v0.y * inv, v0.z * inv, v0.w * inv,
                    v1.x * inv, v1.y * inv, v1.z * inv, v1.w * inv };
    const size_t off[2] = { base + t * 4, base + 1024 + t * 4 };
#pragma unroll
    for (int g = 0; g < 2; g++) {
#pragma unroll
        for (int j = 0; j < 4; j += 2) {
            __nv_bfloat162 hh, ll;
            bf_split2(vv[g * 4 + j], vv[g * 4 + j + 1], hh, ll);
            *(__nv_bfloat162*)(Ah + off[g] + j) = hh;
            *(__nv_bfloat162*)(Al + off[g] + j) = ll;
        }
    }
}

// ---------------------------------------------------------------------------
// Launch
// ---------------------------------------------------------------------------
extern "C" void kernel_launch(void* const* d_in, const int* in_sizes, int n_in,
                              void* d_out, int out_size)
{
    const float* query = (const float*)d_in[0];
    const float* key   = (const float*)d_in[1];
    const float* value = (const float*)d_in[2];
    const float* Wq    = (const float*)d_in[3];
    const float* bq    = (const float*)d_in[4];
    const float* Wk    = (const float*)d_in[5];
    const float* bk    = (const float*)d_in[6];
    const float* Wv    = (const float*)d_in[7];
    const float* bv    = (const float*)d_in[8];
    float* out = (float*)d_out;

    __nv_bfloat16 *xh, *xl, *wh, *wl, *qkvh, *qkvl, *vth, *vtl, *ah, *al;
    float *sf, *bias;
    cudaGetSymbolAddress((void**)&xh, g_xh);
    cudaGetSymbolAddress((void**)&xl, g_xl);
    cudaGetSymbolAddress((void**)&wh, g_wh);
    cudaGetSymbolAddress((void**)&wl, g_wl);
    cudaGetSymbolAddress((void**)&bias, g_bias);
    cudaGetSymbolAddress((void**)&qkvh, g_qkvh);
    cudaGetSymbolAddress((void**)&qkvl, g_qkvl);
    cudaGetSymbolAddress((void**)&vth, g_vth);
    cudaGetSymbolAddress((void**)&vtl, g_vtl);
    cudaGetSymbolAddress((void**)&sf, g_sf);
    cudaGetSymbolAddress((void**)&ah, g_ah);
    cudaGetSymbolAddress((void**)&al, g_al);

    cudaFuncSetAttribute((const void*)gemm_ld<0>,
                         cudaFuncAttributeMaxDynamicSharedMemorySize, SMEM_TOTAL);
    cudaFuncSetAttribute((const void*)gemm_ld<2>,
                         cudaFuncAttributeMaxDynamicSharedMemorySize, SMEM_TOTAL);

    const long PD = (long)MTOT * DIM;     // per-z projection stride
    const int nIn4 = MTOT * DIM / 4;

    // ---- Gather biases into one buffer (capturable D2D async copies) ----
    cudaMemcpyAsync(bias,            bq, DIM * sizeof(float), cudaMemcpyDeviceToDevice);
    cudaMemcpyAsync(bias + DIM,      bk, DIM * sizeof(float), cudaMemcpyDeviceToDevice);
    cudaMemcpyAsync(bias + 2 * DIM,  bv, DIM * sizeof(float), cudaMemcpyDeviceToDevice);

    // ---- Split inputs (batched z=3) and weights (split+transpose, z=3) ----
    split3<<<dim3(nIn4 / 256, 1, 3), 256>>>(query, key, value, xh, xl, nIn4);
    wsplitT3<<<dim3(DIM / 32, DIM / 32, 3), dim3(32, 8)>>>(Wq, Wk, Wv, wh, wl, DIM, DIM);

    // ---- Batched projections: z=3, emits bf16 hi/lo + bias directly ----
    gemm_ld<2><<<dim3(DIM / 128, MTOT / 128, 3), 256, SMEM_TOTAL>>>(
        xh, xl, PD, wh, wl, (long)DIM * DIM, bias, DIM,
        nullptr, qkvh, qkvl, PD, DIM, DIM);

    // ---- Transpose V (bf16 hi/lo) to [z][D][S] ----
    vtransT<<<dim3(DIM / 32, SEQ / 32, BATCH), dim3(32, 8)>>>(
        qkvh + 2 * PD, qkvl + 2 * PD, vth, vtl);

    // ---- Scores: sf[z] = q[z] @ k[z]^T (fp32) ----
    gemm_ld<0><<<dim3(SEQ / 128, SEQ / 128, BATCH), 256, SMEM_TOTAL>>>(
        qkvh, qkvl, (long)SEQ * DIM, qkvh + PD, qkvl + PD, (long)SEQ * DIM,
        nullptr, 0, sf, nullptr, nullptr, (long)SEQ * SEQ, DIM, SEQ);

    // ---- Softmax (beta folded) fused with bf16 split ----
    softmax_split<<<BATCH * SEQ, 256>>>(sf, ah, al);

    // ---- Out: out[z] = A[z] @ v[z] ----
    gemm_ld<0><<<dim3(DIM / 128, SEQ / 128, BATCH), 256, SMEM_TOTAL>>>(
        ah, al, (long)SEQ * SEQ, vth, vtl, (long)SEQ * DIM,
        nullptr, 0, out, nullptr, nullptr, (long)SEQ * DIM, SEQ, DIM);
}

// round 6
// speedup vs baseline: 1.1659x; 1.1659x over previous
#include <cuda_runtime.h>
#include <cuda_bf16.h>
#include <stdint.h>
#include <math.h>

// Problem constants
#define BATCH 4
#define SEQ   2048
#define DIM   1024
#define MTOT  (BATCH * SEQ)      // 8192
#define BETA  0.03125f

// GEMM tiling: 128x128 CTA tile, K-chunk 32, padded rows (40 elems = 80B)
#define KC       32
#define RSTRIDE  80                  // bytes per smem row (32 elems data + 16B pad)
#define TILE_B   (128 * RSTRIDE)     // 10240 B per tile
#define STAGE_B  (4 * TILE_B)        // Ah | Al | Bh | Bl = 40960 B
#define SMEM_TOTAL (2 * STAGE_B)     // 81920 B (2 stages) -> 2 CTAs/SM possible

// ---------------------------------------------------------------------------
// Scratch (__device__ globals; allocation-free rule)
// ---------------------------------------------------------------------------
__device__ __align__(16) __nv_bfloat16 g_xh[3 * MTOT * DIM], g_xl[3 * MTOT * DIM];
__device__ __align__(16) __nv_bfloat16 g_wh[3 * DIM * DIM],  g_wl[3 * DIM * DIM];
__device__ __align__(16) float         g_bias[3 * DIM];
__device__ __align__(16) __nv_bfloat16 g_qkvh[3 * MTOT * DIM], g_qkvl[3 * MTOT * DIM];
__device__ __align__(16) __nv_bfloat16 g_vth[MTOT * DIM], g_vtl[MTOT * DIM];
__device__ __align__(16) float         g_sf[(size_t)BATCH * SEQ * SEQ];
__device__ __align__(16) __nv_bfloat16 g_ah[(size_t)BATCH * SEQ * SEQ];
__device__ __align__(16) __nv_bfloat16 g_al[(size_t)BATCH * SEQ * SEQ];

// ---------------------------------------------------------------------------
// Helpers
// ---------------------------------------------------------------------------
__device__ __forceinline__ uint32_t s2u(const void* p) {
    return (uint32_t)__cvta_generic_to_shared(p);
}
__device__ __forceinline__ void cp16(uint32_t s, const void* g) {
    asm volatile("cp.async.cg.shared.global [%0], [%1], 16;" :: "r"(s), "l"(g));
}
__device__ __forceinline__ void bf_split2(float a, float b,
                                          __nv_bfloat162& hh, __nv_bfloat162& ll) {
    __nv_bfloat16 ha = __float2bfloat16(a), hb = __float2bfloat16(b);
    hh.x = ha; hh.y = hb;
    ll.x = __float2bfloat16(a - __bfloat162float(ha));
    ll.y = __float2bfloat16(b - __bfloat162float(hb));
}

#define LDSM4(r, addr)                                                        \
    asm volatile("ldmatrix.sync.aligned.m8n8.x4.shared.b16 {%0,%1,%2,%3}, [%4];" \
                 : "=r"((r)[0]), "=r"((r)[1]), "=r"((r)[2]), "=r"((r)[3])     \
                 : "r"(addr))

#define MMA_BF16(d, a, b)                                                     \
    asm volatile(                                                             \
        "mma.sync.aligned.m16n8k16.row.col.f32.bf16.bf16.f32 "                \
        "{%0,%1,%2,%3}, {%4,%5,%6,%7}, {%8,%9}, {%0,%1,%2,%3};\n"             \
        : "+f"((d)[0]), "+f"((d)[1]), "+f"((d)[2]), "+f"((d)[3])              \
        : "r"((a)[0]), "r"((a)[1]), "r"((a)[2]), "r"((a)[3]),                 \
          "r"((b)[0]), "r"((b)[1]))

// ---------------------------------------------------------------------------
// GEMM: C[M,N] = A[M,K] @ B[N,K]^T (+bias), bf16 hi/lo 3-pass, fp32 accum.
// A: m x k row-major (k contig), B: n x k row-major. Grid (N/128, M/128, z).
// EPI: 0 = fp32, 2 = bf16 hi/lo split + bias
// R4 memory layout (KC=32, 80B rows, 2 CTAs/SM) + ldmatrix fragment loads.
// 80B row stride is conflict-free for ldmatrix: row starts hit banks
// 4*(20i mod 32) = all-distinct, 16B widths tile all 32 banks.
// ---------------------------------------------------------------------------
template <int EPI>
__global__ void __launch_bounds__(256, 2) gemm_ld(
    const __nv_bfloat16* __restrict__ Ahi, const __nv_bfloat16* __restrict__ Alo, long sA,
    const __nv_bfloat16* __restrict__ Bhi, const __nv_bfloat16* __restrict__ Blo, long sB,
    const float* __restrict__ bias, int biasStride,
    float* __restrict__ C, __nv_bfloat16* __restrict__ Chi,
    __nv_bfloat16* __restrict__ Clo, long sC,
    int K, int ldc)
{
    extern __shared__ __align__(128) char smem[];
    const uint32_t sb0 = s2u(smem);

    const int t = threadIdx.x;
    const int lane = t & 31;
    const int warp = t >> 5;
    const int wm = warp >> 2;            // 0..1 -> 64 rows
    const int wn = warp & 3;             // 0..3 -> 32 cols
    const int bz = blockIdx.z;

    const size_t aBase = (size_t)bz * sA + (size_t)blockIdx.y * 128 * K;
    const size_t bBase = (size_t)bz * sB + (size_t)blockIdx.x * 128 * K;

    // ldmatrix lane constants (x4: lane l supplies row for matrix l/8)
    const int m4 = lane >> 3;
    const int rA = ((m4 & 1) << 3) + (lane & 7);   // A: m0/m1 = rows, m2/m3 = k+8 half
    const int kA = (m4 >> 1) << 4;                 // byte offset 0 / 16
    const int rB = ((m4 >> 1) << 3) + (lane & 7);  // B: m0/m1 = k halves, m2/m3 = n+8
    const int kB = (m4 & 1) << 4;

    auto load_stage = [&](int st, int k0) {
        const uint32_t so = sb0 + st * STAGE_B;
#pragma unroll
        for (int i = 0; i < 2; i++) {
            int id = t + i * 256;            // 512 ids = 128 rows x 4 16B chunks
            int row = id >> 2;
            int c4 = id & 3;
            uint32_t sw = row * RSTRIDE + c4 * 16;
            size_t ga = aBase + (size_t)row * K + k0 + c4 * 8;
            size_t gb = bBase + (size_t)row * K + k0 + c4 * 8;
            cp16(so + sw,              Ahi + ga);
            cp16(so + TILE_B + sw,     Alo + ga);
            cp16(so + 2 * TILE_B + sw, Bhi + gb);
            cp16(so + 3 * TILE_B + sw, Blo + gb);
        }
        asm volatile("cp.async.commit_group;" ::: "memory");
    };

    float acc[4][4][4] = {};
    const int nk = K / KC;
    load_stage(0, 0);

    for (int kt = 0; kt < nk; kt++) {
        if (kt + 1 < nk) {
            load_stage((kt + 1) & 1, (kt + 1) * KC);
            asm volatile("cp.async.wait_group 1;" ::: "memory");
        } else {
            asm volatile("cp.async.wait_group 0;" ::: "memory");
        }
        __syncthreads();

        const uint32_t st = sb0 + (kt & 1) * STAGE_B;
#pragma unroll
        for (int s = 0; s < 2; s++) {            // two k16 steps per chunk
            const int kb = s * 32;               // byte offset within 64B row data
            uint32_t ah[4][4], al[4][4], bh[2][4], bl[2][4];
#pragma unroll
            for (int mi = 0; mi < 4; mi++) {
                int row = wm * 64 + mi * 16 + rA;
                uint32_t ad = st + row * RSTRIDE + kb + kA;
                LDSM4(ah[mi], ad);
                LDSM4(al[mi], ad + TILE_B);
            }
#pragma unroll
            for (int nt = 0; nt < 2; nt++) {
                int row = wn * 32 + nt * 16 + rB;
                uint32_t ad = st + 2 * TILE_B + row * RSTRIDE + kb + kB;
                LDSM4(bh[nt], ad);
                LDSM4(bl[nt], ad + TILE_B);
            }
#pragma unroll
            for (int mi = 0; mi < 4; mi++)
#pragma unroll
                for (int ni = 0; ni < 4; ni++) {
                    const uint32_t* bph = &bh[ni >> 1][(ni & 1) * 2];
                    const uint32_t* bpl = &bl[ni >> 1][(ni & 1) * 2];
                    MMA_BF16(acc[mi][ni], ah[mi], bph);
                    MMA_BF16(acc[mi][ni], ah[mi], bpl);
                    MMA_BF16(acc[mi][ni], al[mi], bph);
                }
        }
        __syncthreads();
    }

    // Epilogue
    const int r = lane >> 2;
    const int cq = lane & 3;
    const int row0 = blockIdx.y * 128 + wm * 64;
    const int col0 = blockIdx.x * 128 + wn * 32;
    const size_t zC = (size_t)bz * sC;

#pragma unroll
    for (int mi = 0; mi < 4; mi++) {
#pragma unroll
        for (int ni = 0; ni < 4; ni++) {
            int rr = row0 + mi * 16 + r;
            int cc = col0 + ni * 8 + 2 * cq;
            if (EPI == 2) {
                float b0 = bias[bz * biasStride + cc];
                float b1 = bias[bz * biasStride + cc + 1];
                __nv_bfloat162 hh, ll;
                bf_split2(acc[mi][ni][0] + b0, acc[mi][ni][1] + b1, hh, ll);
                *(__nv_bfloat162*)(Chi + zC + (size_t)rr * ldc + cc) = hh;
                *(__nv_bfloat162*)(Clo + zC + (size_t)rr * ldc + cc) = ll;
                bf_split2(acc[mi][ni][2] + b0, acc[mi][ni][3] + b1, hh, ll);
                *(__nv_bfloat162*)(Chi + zC + (size_t)(rr + 8) * ldc + cc) = hh;
                *(__nv_bfloat162*)(Clo + zC + (size_t)(rr + 8) * ldc + cc) = ll;
            } else {
                float* Cp = C + zC;
                float2 v0 = make_float2(acc[mi][ni][0], acc[mi][ni][1]);
                float2 v1 = make_float2(acc[mi][ni][2], acc[mi][ni][3]);
                *(float2*)(Cp + (size_t)rr * ldc + cc) = v0;
                *(float2*)(Cp + (size_t)(rr + 8) * ldc + cc) = v1;
            }
        }
    }
}

// ---------------------------------------------------------------------------
// Batched elementwise split: 3 fp32 sources -> hi/lo bf16 (z picks source)
// ---------------------------------------------------------------------------
__global__ void __launch_bounds__(256) split3(
    const float* __restrict__ s0, const float* __restrict__ s1,
    const float* __restrict__ s2, __nv_bfloat16* __restrict__ hi,
    __nv_bfloat16* __restrict__ lo, int n4each)
{
    const int z = blockIdx.z;
    const float* x = (z == 0) ? s0 : (z == 1) ? s1 : s2;
    int i = blockIdx.x * 256 + threadIdx.x;
    if (i >= n4each) return;
    float4 v = ((const float4*)x)[i];
    __nv_bfloat162 h0, l0, h1, l1;
    bf_split2(v.x, v.y, h0, l0);
    bf_split2(v.z, v.w, h1, l1);
    size_t base = (size_t)z * n4each * 2;
    ((__nv_bfloat162*)hi)[base + 2 * i]     = h0;
    ((__nv_bfloat162*)hi)[base + 2 * i + 1] = h1;
    ((__nv_bfloat162*)lo)[base + 2 * i]     = l0;
    ((__nv_bfloat162*)lo)[base + 2 * i + 1] = l1;
}

// ---------------------------------------------------------------------------
// Batched split + transpose: W_z[R][C] fp32 -> hi/lo[z][C][R] bf16
// ---------------------------------------------------------------------------
__global__ void __launch_bounds__(256) wsplitT3(
    const float* __restrict__ s0, const float* __restrict__ s1,
    const float* __restrict__ s2, __nv_bfloat16* __restrict__ hi,
    __nv_bfloat16* __restrict__ lo, int R, int Ccols)
{
    __shared__ float tile[32][33];
    const int z = blockIdx.z;
    const float* xp = (z == 0) ? s0 : (z == 1) ? s1 : s2;
    const size_t zo = (size_t)z * R * Ccols;
    const int c0 = blockIdx.x * 32, r0 = blockIdx.y * 32;
    const int tx = threadIdx.x, ty = threadIdx.y;
#pragma unroll
    for (int i = 0; i < 32; i += 8)
        tile[ty + i][tx] = xp[(size_t)(r0 + ty + i) * Ccols + c0 + tx];
    __syncthreads();
#pragma unroll
    for (int i = 0; i < 32; i += 8) {
        float v = tile[tx][ty + i];
        __nv_bfloat16 h = __float2bfloat16(v);
        __nv_bfloat16 l = __float2bfloat16(v - __bfloat162float(h));
        size_t o = zo + (size_t)(c0 + ty + i) * R + r0 + tx;
        hi[o] = h;
        lo[o] = l;
    }
}

// ---------------------------------------------------------------------------
// bf16 hi+lo transpose: v[z][S][D] -> vt[z][D][S]
// ---------------------------------------------------------------------------
__global__ void __launch_bounds__(256) vtransT(
    const __nv_bfloat16* __restrict__ vh, const __nv_bfloat16* __restrict__ vl,
    __nv_bfloat16* __restrict__ vth, __nv_bfloat16* __restrict__ vtl)
{
    __shared__ __nv_bfloat16 th[32][33], tl[32][33];
    const int z = blockIdx.z;
    const int c0 = blockIdx.x * 32, r0 = blockIdx.y * 32;
    const int tx = threadIdx.x, ty = threadIdx.y;
    const size_t inz = (size_t)z * SEQ * DIM;
#pragma unroll
    for (int i = 0; i < 32; i += 8) {
        size_t o = inz + (size_t)(r0 + ty + i) * DIM + c0 + tx;
        th[ty + i][tx] = vh[o];
        tl[ty + i][tx] = vl[o];
    }
    __syncthreads();
#pragma unroll
    for (int i = 0; i < 32; i += 8) {
        size_t o = inz + (size_t)(c0 + ty + i) * SEQ + r0 + tx;
        vth[o] = th[tx][ty + i];
        vtl[o] = tl[tx][ty + i];
    }
}

// ---------------------------------------------------------------------------
// Row softmax (BETA folded) fused with bf16 hi/lo split output
// ---------------------------------------------------------------------------
__global__ void __launch_bounds__(256) softmax_split(
    const float* __restrict__ S, __nv_bfloat16* __restrict__ Ah,
    __nv_bfloat16* __restrict__ Al)
{
    __shared__ float red[256];
    const int t = threadIdx.x;
    const size_t base = (size_t)blockIdx.x * SEQ;
    const float* p = S + base;

    float4 v0 = *(const float4*)(p + t * 4);
    float4 v1 = *(const float4*)(p + 1024 + t * 4);
    v0.x *= BETA; v0.y *= BETA; v0.z *= BETA; v0.w *= BETA;
    v1.x *= BETA; v1.y *= BETA; v1.z *= BETA; v1.w *= BETA;

    float m = fmaxf(fmaxf(fmaxf(v0.x, v0.y), fmaxf(v0.z, v0.w)),
                    fmaxf(fmaxf(v1.x, v1.y), fmaxf(v1.z, v1.w)));
    red[t] = m;
    __syncthreads();
    for (int s = 128; s > 0; s >>= 1) {
        if (t < s) red[t] = fmaxf(red[t], red[t + s]);
        __syncthreads();
    }
    m = red[0];
    __syncthreads();

    v0.x = __expf(v0.x - m); v0.y = __expf(v0.y - m);
    v0.z = __expf(v0.z - m); v0.w = __expf(v0.w - m);
    v1.x = __expf(v1.x - m); v1.y = __expf(v1.y - m);
    v1.z = __expf(v1.z - m); v1.w = __expf(v1.w - m);

    float sum = (v0.x + v0.y) + (v0.z + v0.w) + (v1.x + v1.y) + (v1.z + v1.w);
    red[t] = sum;
    __syncthreads();
    for (int s = 128; s > 0; s >>= 1) {
        if (t < s) red[t] += red[t + s];
        __syncthreads();
    }
    const float inv = 1.0f / red[0];

    float vv[8] = { v0.x * inv, v0.y * inv, v0.z * inv, v0.w * inv,
                    v1.x * inv, v1.y * inv, v1.z * inv, v1.w * inv };
    const size_t off[2] = { base + t * 4, base + 1024 + t * 4 };
#pragma unroll
    for (int g = 0; g < 2; g++) {
#pragma unroll
        for (int j = 0; j < 4; j += 2) {
            __nv_bfloat162 hh, ll;
            bf_split2(vv[g * 4 + j], vv[g * 4 + j + 1], hh, ll);
            *(__nv_bfloat162*)(Ah + off[g] + j) = hh;
            *(__nv_bfloat162*)(Al + off[g] + j) = ll;
        }
    }
}

// ---------------------------------------------------------------------------
// Launch
// ---------------------------------------------------------------------------
extern "C" void kernel_launch(void* const* d_in, const int* in_sizes, int n_in,
                              void* d_out, int out_size)
{
    const float* query = (const float*)d_in[0];
    const float* key   = (const float*)d_in[1];
    const float* value = (const float*)d_in[2];
    const float* Wq    = (const float*)d_in[3];
    const float* bq    = (const float*)d_in[4];
    const float* Wk    = (const float*)d_in[5];
    const float* bk    = (const float*)d_in[6];
    const float* Wv    = (const float*)d_in[7];
    const float* bv    = (const float*)d_in[8];
    float* out = (float*)d_out;

    __nv_bfloat16 *xh, *xl, *wh, *wl, *qkvh, *qkvl, *vth, *vtl, *ah, *al;
    float *sf, *bias;
    cudaGetSymbolAddress((void**)&xh, g_xh);
    cudaGetSymbolAddress((void**)&xl, g_xl);
    cudaGetSymbolAddress((void**)&wh, g_wh);
    cudaGetSymbolAddress((void**)&wl, g_wl);
    cudaGetSymbolAddress((void**)&bias, g_bias);
    cudaGetSymbolAddress((void**)&qkvh, g_qkvh);
    cudaGetSymbolAddress((void**)&qkvl, g_qkvl);
    cudaGetSymbolAddress((void**)&vth, g_vth);
    cudaGetSymbolAddress((void**)&vtl, g_vtl);
    cudaGetSymbolAddress((void**)&sf, g_sf);
    cudaGetSymbolAddress((void**)&ah, g_ah);
    cudaGetSymbolAddress((void**)&al, g_al);

    cudaFuncSetAttribute((const void*)gemm_ld<0>,
                         cudaFuncAttributeMaxDynamicSharedMemorySize, SMEM_TOTAL);
    cudaFuncSetAttribute((const void*)gemm_ld<2>,
                         cudaFuncAttributeMaxDynamicSharedMemorySize, SMEM_TOTAL);

    const long PD = (long)MTOT * DIM;     // per-z projection stride
    const int nIn4 = MTOT * DIM / 4;

    // ---- Gather biases into one buffer (capturable D2D async copies) ----
    cudaMemcpyAsync(bias,            bq, DIM * sizeof(float), cudaMemcpyDeviceToDevice);
    cudaMemcpyAsync(bias + DIM,      bk, DIM * sizeof(float), cudaMemcpyDeviceToDevice);
    cudaMemcpyAsync(bias + 2 * DIM,  bv, DIM * sizeof(float), cudaMemcpyDeviceToDevice);

    // ---- Split inputs (batched z=3) and weights (split+transpose, z=3) ----
    split3<<<dim3(nIn4 / 256, 1, 3), 256>>>(query, key, value, xh, xl, nIn4);
    wsplitT3<<<dim3(DIM / 32, DIM / 32, 3), dim3(32, 8)>>>(Wq, Wk, Wv, wh, wl, DIM, DIM);

    // ---- Batched projections: z=3, emits bf16 hi/lo + bias directly ----
    gemm_ld<2><<<dim3(DIM / 128, MTOT / 128, 3), 256, SMEM_TOTAL>>>(
        xh, xl, PD, wh, wl, (long)DIM * DIM, bias, DIM,
        nullptr, qkvh, qkvl, PD, DIM, DIM);

    // ---- Transpose V (bf16 hi/lo) to [z][D][S] ----
    vtransT<<<dim3(DIM / 32, SEQ / 32, BATCH), dim3(32, 8)>>>(
        qkvh + 2 * PD, qkvl + 2 * PD, vth, vtl);

    // ---- Scores: sf[z] = q[z] @ k[z]^T (fp32) ----
    gemm_ld<0><<<dim3(SEQ / 128, SEQ / 128, BATCH), 256, SMEM_TOTAL>>>(
        qkvh, qkvl, (long)SEQ * DIM, qkvh + PD, qkvl + PD, (long)SEQ * DIM,
        nullptr, 0, sf, nullptr, nullptr, (long)SEQ * SEQ, DIM, SEQ);

    // ---- Softmax (beta folded) fused with bf16 split ----
    softmax_split<<<BATCH * SEQ, 256>>>(sf, ah, al);

    // ---- Out: out[z] = A[z] @ v[z] ----
    gemm_ld<0><<<dim3(DIM / 128, SEQ / 128, BATCH), 256, SMEM_TOTAL>>>(
        ah, al, (long)SEQ * SEQ, vth, vtl, (long)SEQ * DIM,
        nullptr, 0, out, nullptr, nullptr, (long)SEQ * DIM, SEQ, DIM);
}

// round 7
// speedup vs baseline: 1.4879x; 1.2762x over previous
#include <cuda_runtime.h>
#include <cuda_fp16.h>
#include <stdint.h>
#include <math.h>

// Problem constants
#define BATCH 4
#define SEQ   2048
#define DIM   1024
#define MTOT  (BATCH * SEQ)      // 8192
#define BETA  0.03125f

// GEMM tiling (R4-proven): 128x128 CTA tile, K-chunk 32, 80B padded rows
#define KC       32
#define RSTRIDE  80                  // bytes per smem row (32 fp16 + 16B pad)
#define TILE_B   (128 * RSTRIDE)     // 10240 B
#define STAGE_B  (3 * TILE_B)        // A | Bh | Bl = 30720 B
#define SMEM_TOTAL (2 * STAGE_B)     // 61440 B, 2 stages

// ---------------------------------------------------------------------------
// Scratch (__device__ globals; allocation-free rule)
// ---------------------------------------------------------------------------
__device__ __align__(16) __half g_x[3 * MTOT * DIM];             // fp16 inputs (single)
__device__ __align__(16) __half g_wh[3 * DIM * DIM], g_wl[3 * DIM * DIM];
__device__ __align__(16) float  g_bias[3 * DIM];
__device__ __align__(16) __half g_qkvh[3 * MTOT * DIM], g_qkvl[3 * MTOT * DIM];
__device__ __align__(16) __half g_vth[MTOT * DIM], g_vtl[MTOT * DIM];
__device__ __align__(16) float  g_sf[(size_t)BATCH * SEQ * SEQ];
__device__ __align__(16) __half g_p[(size_t)BATCH * SEQ * SEQ];  // probs (single)

// ---------------------------------------------------------------------------
// Helpers
// ---------------------------------------------------------------------------
__device__ __forceinline__ uint32_t s2u(const void* p) {
    return (uint32_t)__cvta_generic_to_shared(p);
}
__device__ __forceinline__ void cp16(uint32_t s, const void* g) {
    asm volatile("cp.async.cg.shared.global [%0], [%1], 16;" :: "r"(s), "l"(g));
}
__device__ __forceinline__ void h_split2(float a, float b, __half2& hh, __half2& ll) {
    __half ha = __float2half(a), hb = __float2half(b);
    hh.x = ha; hh.y = hb;
    ll.x = __float2half(a - __half2float(ha));
    ll.y = __float2half(b - __half2float(hb));
}

#define MMA_F16(d, a, b)                                                      \
    asm volatile(                                                             \
        "mma.sync.aligned.m16n8k16.row.col.f32.f16.f16.f32 "                  \
        "{%0,%1,%2,%3}, {%4,%5,%6,%7}, {%8,%9}, {%0,%1,%2,%3};\n"             \
        : "+f"((d)[0]), "+f"((d)[1]), "+f"((d)[2]), "+f"((d)[3])              \
        : "r"((a)[0]), "r"((a)[1]), "r"((a)[2]), "r"((a)[3]),                 \
          "r"((b)[0]), "r"((b)[1]))

// ---------------------------------------------------------------------------
// GEMM: C[M,N] = A[M,K] @ B[N,K]^T (+bias), fp32 accum.
// A: single fp16 (m x k). B: fp16 hi/lo (n x k). 2 mma passes: A*Bh + A*Bl.
// Grid (N/128, M/128, z). EPI: 0 = fp32 out, 2 = fp16 hi/lo split + bias.
// R4-proven memory config: KC=32, 80B rows, scalar LDS fragments, 2-stage.
// ---------------------------------------------------------------------------
template <int EPI>
__global__ void __launch_bounds__(256) gemm_hl(
    const __half* __restrict__ A, long sA,
    const __half* __restrict__ Bhi, const __half* __restrict__ Blo, long sB,
    const float* __restrict__ bias, int biasStride,
    float* __restrict__ C, __half* __restrict__ Chi, __half* __restrict__ Clo,
    long sC, int K, int ldc)
{
    extern __shared__ __align__(128) char smem[];
    const uint32_t sb0 = s2u(smem);

    const int t = threadIdx.x;
    const int lane = t & 31;
    const int warp = t >> 5;
    const int wm = warp >> 2;            // 0..1 -> 64 rows
    const int wn = warp & 3;             // 0..3 -> 32 cols
    const int bz = blockIdx.z;
    const int r = lane >> 2;             // 0..7
    const int cq = lane & 3;             // 0..3

    const size_t aBase = (size_t)bz * sA + (size_t)blockIdx.y * 128 * K;
    const size_t bBase = (size_t)bz * sB + (size_t)blockIdx.x * 128 * K;

    auto load_stage = [&](int st, int k0) {
        const uint32_t so = sb0 + st * STAGE_B;
#pragma unroll
        for (int i = 0; i < 2; i++) {
            int id = t + i * 256;            // 512 ids = 128 rows x 4 16B chunks
            int row = id >> 2;
            int c4 = id & 3;
            uint32_t sw = row * RSTRIDE + c4 * 16;
            size_t ga = aBase + (size_t)row * K + k0 + c4 * 8;
            size_t gb = bBase + (size_t)row * K + k0 + c4 * 8;
            cp16(so + sw,              A   + ga);
            cp16(so + TILE_B + sw,     Bhi + gb);
            cp16(so + 2 * TILE_B + sw, Blo + gb);
        }
        asm volatile("cp.async.commit_group;" ::: "memory");
    };

    float acc[4][4][4] = {};
    const int nk = K / KC;
    load_stage(0, 0);

    for (int kt = 0; kt < nk; kt++) {
        if (kt + 1 < nk) {
            load_stage((kt + 1) & 1, (kt + 1) * KC);
            asm volatile("cp.async.wait_group 1;" ::: "memory");
        } else {
            asm volatile("cp.async.wait_group 0;" ::: "memory");
        }
        __syncthreads();

        const uint32_t* sb = (const uint32_t*)(smem + (kt & 1) * STAGE_B);
        // u32-unit geometry: row stride 20, tile 2560, k+8 -> +4, +8 rows -> +160
#pragma unroll
        for (int kk = 0; kk < 2; kk++) {
            uint32_t ah[4][4], bh[4][2], bl[4][2];
#pragma unroll
            for (int mi = 0; mi < 4; mi++) {
                int row = wm * 64 + mi * 16 + r;
                int base = row * 20 + kk * 8 + cq;
                ah[mi][0] = sb[base];       ah[mi][1] = sb[base + 160];
                ah[mi][2] = sb[base + 4];   ah[mi][3] = sb[base + 164];
            }
#pragma unroll
            for (int ni = 0; ni < 4; ni++) {
                int row = wn * 32 + ni * 8 + r;
                int base = row * 20 + kk * 8 + cq;
                bh[ni][0] = sb[2560 + base];  bh[ni][1] = sb[2560 + base + 4];
                bl[ni][0] = sb[5120 + base];  bl[ni][1] = sb[5120 + base + 4];
            }
#pragma unroll
            for (int mi = 0; mi < 4; mi++)
#pragma unroll
                for (int ni = 0; ni < 4; ni++) {
                    MMA_F16(acc[mi][ni], ah[mi], bh[ni]);
                    MMA_F16(acc[mi][ni], ah[mi], bl[ni]);
                }
        }
        __syncthreads();
    }

    // Epilogue
    const int row0 = blockIdx.y * 128 + wm * 64;
    const int col0 = blockIdx.x * 128 + wn * 32;
    const size_t zC = (size_t)bz * sC;

#pragma unroll
    for (int mi = 0; mi < 4; mi++) {
#pragma unroll
        for (int ni = 0; ni < 4; ni++) {
            int rr = row0 + mi * 16 + r;
            int cc = col0 + ni * 8 + 2 * cq;
            if (EPI == 2) {
                float b0 = bias[bz * biasStride + cc];
                float b1 = bias[bz * biasStride + cc + 1];
                __half2 hh, ll;
                h_split2(acc[mi][ni][0] + b0, acc[mi][ni][1] + b1, hh, ll);
                *(__half2*)(Chi + zC + (size_t)rr * ldc + cc) = hh;
                *(__half2*)(Clo + zC + (size_t)rr * ldc + cc) = ll;
                h_split2(acc[mi][ni][2] + b0, acc[mi][ni][3] + b1, hh, ll);
                *(__half2*)(Chi + zC + (size_t)(rr + 8) * ldc + cc) = hh;
                *(__half2*)(Clo + zC + (size_t)(rr + 8) * ldc + cc) = ll;
            } else {
                float* Cp = C + zC;
                float2 v0 = make_float2(acc[mi][ni][0], acc[mi][ni][1]);
                float2 v1 = make_float2(acc[mi][ni][2], acc[mi][ni][3]);
                *(float2*)(Cp + (size_t)rr * ldc + cc) = v0;
                *(float2*)(Cp + (size_t)(rr + 8) * ldc + cc) = v1;
            }
        }
    }
}

// ---------------------------------------------------------------------------
// Batched elementwise convert: 3 fp32 sources -> single fp16
// ---------------------------------------------------------------------------
__global__ void __launch_bounds__(256) cvt3(
    const float* __restrict__ s0, const float* __restrict__ s1,
    const float* __restrict__ s2, __half* __restrict__ dst, int n4each)
{
    const int z = blockIdx.z;
    const float* x = (z == 0) ? s0 : (z == 1) ? s1 : s2;
    int i = blockIdx.x * 256 + threadIdx.x;
    if (i >= n4each) return;
    float4 v = ((const float4*)x)[i];
    __half2 h0, h1;
    h0.x = __float2half(v.x); h0.y = __float2half(v.y);
    h1.x = __float2half(v.z); h1.y = __float2half(v.w);
    size_t base = (size_t)z * n4each * 2;
    ((__half2*)dst)[base + 2 * i]     = h0;
    ((__half2*)dst)[base + 2 * i + 1] = h1;
}

// ---------------------------------------------------------------------------
// Batched split + transpose: W_z[R][C] fp32 -> hi/lo[z][C][R] fp16
// ---------------------------------------------------------------------------
__global__ void __launch_bounds__(256) wsplitT3(
    const float* __restrict__ s0, const float* __restrict__ s1,
    const float* __restrict__ s2, __half* __restrict__ hi,
    __half* __restrict__ lo, int R, int Ccols)
{
    __shared__ float tile[32][33];
    const int z = blockIdx.z;
    const float* xp = (z == 0) ? s0 : (z == 1) ? s1 : s2;
    const size_t zo = (size_t)z * R * Ccols;
    const int c0 = blockIdx.x * 32, r0 = blockIdx.y * 32;
    const int tx = threadIdx.x, ty = threadIdx.y;
#pragma unroll
    for (int i = 0; i < 32; i += 8)
        tile[ty + i][tx] = xp[(size_t)(r0 + ty + i) * Ccols + c0 + tx];
    __syncthreads();
#pragma unroll
    for (int i = 0; i < 32; i += 8) {
        float v = tile[tx][ty + i];
        __half h = __float2half(v);
        __half l = __float2half(v - __half2float(h));
        size_t o = zo + (size_t)(c0 + ty + i) * R + r0 + tx;
        hi[o] = h;
        lo[o] = l;
    }
}

// ---------------------------------------------------------------------------
// fp16 hi+lo transpose: v[z][S][D] -> vt[z][D][S]
// ---------------------------------------------------------------------------
__global__ void __launch_bounds__(256) vtransT(
    const __half* __restrict__ vh, const __half* __restrict__ vl,
    __half* __restrict__ vth, __half* __restrict__ vtl)
{
    __shared__ __half th[32][33], tl[32][33];
    const int z = blockIdx.z;
    const int c0 = blockIdx.x * 32, r0 = blockIdx.y * 32;
    const int tx = threadIdx.x, ty = threadIdx.y;
    const size_t inz = (size_t)z * SEQ * DIM;
#pragma unroll
    for (int i = 0; i < 32; i += 8) {
        size_t o = inz + (size_t)(r0 + ty + i) * DIM + c0 + tx;
        th[ty + i][tx] = vh[o];
        tl[ty + i][tx] = vl[o];
    }
    __syncthreads();
#pragma unroll
    for (int i = 0; i < 32; i += 8) {
        size_t o = inz + (size_t)(c0 + ty + i) * SEQ + r0 + tx;
        vth[o] = th[tx][ty + i];
        vtl[o] = tl[tx][ty + i];
    }
}

// ---------------------------------------------------------------------------
// Row softmax (BETA folded), emits single fp16 probs
// ---------------------------------------------------------------------------
__global__ void __launch_bounds__(256) softmax_h(
    const float* __restrict__ S, __half* __restrict__ P)
{
    __shared__ float red[256];
    const int t = threadIdx.x;
    const size_t base = (size_t)blockIdx.x * SEQ;
    const float* p = S + base;

    float4 v0 = *(const float4*)(p + t * 4);
    float4 v1 = *(const float4*)(p + 1024 + t * 4);
    v0.x *= BETA; v0.y *= BETA; v0.z *= BETA; v0.w *= BETA;
    v1.x *= BETA; v1.y *= BETA; v1.z *= BETA; v1.w *= BETA;

    float m = fmaxf(fmaxf(fmaxf(v0.x, v0.y), fmaxf(v0.z, v0.w)),
                    fmaxf(fmaxf(v1.x, v1.y), fmaxf(v1.z, v1.w)));
    red[t] = m;
    __syncthreads();
    for (int s = 128; s > 0; s >>= 1) {
        if (t < s) red[t] = fmaxf(red[t], red[t + s]);
        __syncthreads();
    }
    m = red[0];
    __syncthreads();

    v0.x = __expf(v0.x - m); v0.y = __expf(v0.y - m);
    v0.z = __expf(v0.z - m); v0.w = __expf(v0.w - m);
    v1.x = __expf(v1.x - m); v1.y = __expf(v1.y - m);
    v1.z = __expf(v1.z - m); v1.w = __expf(v1.w - m);

    float sum = (v0.x + v0.y) + (v0.z + v0.w) + (v1.x + v1.y) + (v1.z + v1.w);
    red[t] = sum;
    __syncthreads();
    for (int s = 128; s > 0; s >>= 1) {
        if (t < s) red[t] += red[t + s];
        __syncthreads();
    }
    const float inv = 1.0f / red[0];

    __half2 o0, o1, o2, o3;
    o0.x = __float2half(v0.x * inv); o0.y = __float2half(v0.y * inv);
    o1.x = __float2half(v0.z * inv); o1.y = __float2half(v0.w * inv);
    o2.x = __float2half(v1.x * inv); o2.y = __float2half(v1.y * inv);
    o3.x = __float2half(v1.z * inv); o3.y = __float2half(v1.w * inv);
    *(__half2*)(P + base + t * 4)        = o0;
    *(__half2*)(P + base + t * 4 + 2)    = o1;
    *(__half2*)(P + base + 1024 + t * 4)     = o2;
    *(__half2*)(P + base + 1024 + t * 4 + 2) = o3;
}

// ---------------------------------------------------------------------------
// Launch
// ---------------------------------------------------------------------------
extern "C" void kernel_launch(void* const* d_in, const int* in_sizes, int n_in,
                              void* d_out, int out_size)
{
    const float* query = (const float*)d_in[0];
    const float* key   = (const float*)d_in[1];
    const float* value = (const float*)d_in[2];
    const float* Wq    = (const float*)d_in[3];
    const float* bq    = (const float*)d_in[4];
    const float* Wk    = (const float*)d_in[5];
    const float* bk    = (const float*)d_in[6];
    const float* Wv    = (const float*)d_in[7];
    const float* bv    = (const float*)d_in[8];
    float* out = (float*)d_out;

    __half *x, *wh, *wl, *qkvh, *qkvl, *vth, *vtl, *pp;
    float *sf, *bias;
    cudaGetSymbolAddress((void**)&x, g_x);
    cudaGetSymbolAddress((void**)&wh, g_wh);
    cudaGetSymbolAddress((void**)&wl, g_wl);
    cudaGetSymbolAddress((void**)&bias, g_bias);
    cudaGetSymbolAddress((void**)&qkvh, g_qkvh);
    cudaGetSymbolAddress((void**)&qkvl, g_qkvl);
    cudaGetSymbolAddress((void**)&vth, g_vth);
    cudaGetSymbolAddress((void**)&vtl, g_vtl);
    cudaGetSymbolAddress((void**)&sf, g_sf);
    cudaGetSymbolAddress((void**)&pp, g_p);

    cudaFuncSetAttribute((const void*)gemm_hl<0>,
                         cudaFuncAttributeMaxDynamicSharedMemorySize, SMEM_TOTAL);
    cudaFuncSetAttribute((const void*)gemm_hl<2>,
                         cudaFuncAttributeMaxDynamicSharedMemorySize, SMEM_TOTAL);

    const long PD = (long)MTOT * DIM;     // per-z projection stride
    const int nIn4 = MTOT * DIM / 4;

    // ---- Gather biases (capturable D2D async copies) ----
    cudaMemcpyAsync(bias,           bq, DIM * sizeof(float), cudaMemcpyDeviceToDevice);
    cudaMemcpyAsync(bias + DIM,     bk, DIM * sizeof(float), cudaMemcpyDeviceToDevice);
    cudaMemcpyAsync(bias + 2 * DIM, bv, DIM * sizeof(float), cudaMemcpyDeviceToDevice);

    // ---- Inputs -> fp16 single; weights -> fp16 hi/lo transposed ----
    cvt3<<<dim3(nIn4 / 256, 1, 3), 256>>>(query, key, value, x, nIn4);
    wsplitT3<<<dim3(DIM / 32, DIM / 32, 3), dim3(32, 8)>>>(Wq, Wk, Wv, wh, wl, DIM, DIM);

    // ---- Batched projections (z=3): A = x single, B = W hi/lo ----
    gemm_hl<2><<<dim3(DIM / 128, MTOT / 128, 3), 256, SMEM_TOTAL>>>(
        x, PD, wh, wl, (long)DIM * DIM, bias, DIM,
        nullptr, qkvh, qkvl, PD, DIM, DIM);

    // ---- Transpose V (hi/lo) to [z][D][S] ----
    vtransT<<<dim3(DIM / 32, SEQ / 32, BATCH), dim3(32, 8)>>>(
        qkvh + 2 * PD, qkvl + 2 * PD, vth, vtl);

    // ---- Scores: A = q_hi (fp16(q), unsplit), B = k hi/lo ----
    gemm_hl<0><<<dim3(SEQ / 128, SEQ / 128, BATCH), 256, SMEM_TOTAL>>>(
        qkvh, (long)SEQ * DIM, qkvh + PD, qkvl + PD, (long)SEQ * DIM,
        nullptr, 0, sf, nullptr, nullptr, (long)SEQ * SEQ, DIM, SEQ);

    // ---- Softmax (beta folded) -> fp16 probs ----
    softmax_h<<<BATCH * SEQ, 256>>>(sf, pp);

    // ---- Out: A = probs (unsplit), B = v^T hi/lo ----
    gemm_hl<0><<<dim3(DIM / 128, SEQ / 128, BATCH), 256, SMEM_TOTAL>>>(
        pp, (long)SEQ * SEQ, vth, vtl, (long)SEQ * DIM,
        nullptr, 0, out, nullptr, nullptr, (long)SEQ * DIM, SEQ, DIM);
}

// round 8
// speedup vs baseline: 1.5710x; 1.0558x over previous
#include <cuda_runtime.h>
#include <cuda_fp16.h>
#include <stdint.h>
#include <math.h>

// Problem constants
#define BATCH 4
#define SEQ   2048
#define DIM   1024
#define MTOT  (BATCH * SEQ)      // 8192
#define BETA  0.03125f

// GEMM tiling: 128x128 CTA tile, K-chunk 32, 80B padded rows (proven config)
#define KC       32
#define RSTRIDE  80                  // bytes per smem row (32 fp16 + 16B pad)
#define TILE_B   (128 * RSTRIDE)     // 10240 B
#define STAGE_B  (3 * TILE_B)        // A | Bh | Bl = 30720 B
#define SMEM_TOTAL (2 * STAGE_B)     // 61440 B, 2 stages -> 2 CTAs/SM

// ---------------------------------------------------------------------------
// Scratch (__device__ globals; allocation-free rule)
// ---------------------------------------------------------------------------
__device__ __align__(16) __half g_x[3 * MTOT * DIM];             // fp16 inputs (single)
__device__ __align__(16) __half g_wh[3 * DIM * DIM], g_wl[3 * DIM * DIM];
__device__ __align__(16) float  g_bias[3 * DIM];
__device__ __align__(16) __half g_qkvh[3 * MTOT * DIM], g_qkvl[3 * MTOT * DIM];
__device__ __align__(16) __half g_vth[MTOT * DIM], g_vtl[MTOT * DIM];
__device__ __align__(16) float  g_sf[(size_t)BATCH * SEQ * SEQ];
__device__ __align__(16) __half g_p[(size_t)BATCH * SEQ * SEQ];  // probs (single)

// ---------------------------------------------------------------------------
// Helpers
// ---------------------------------------------------------------------------
__device__ __forceinline__ uint32_t s2u(const void* p) {
    return (uint32_t)__cvta_generic_to_shared(p);
}
__device__ __forceinline__ void cp16(uint32_t s, const void* g) {
    asm volatile("cp.async.cg.shared.global [%0], [%1], 16;" :: "r"(s), "l"(g));
}
__device__ __forceinline__ void h_split2(float a, float b, __half2& hh, __half2& ll) {
    __half ha = __float2half(a), hb = __float2half(b);
    hh.x = ha; hh.y = hb;
    ll.x = __float2half(a - __half2float(ha));
    ll.y = __float2half(b - __half2float(hb));
}

#define LDSM4(r, addr)                                                        \
    asm volatile("ldmatrix.sync.aligned.m8n8.x4.shared.b16 {%0,%1,%2,%3}, [%4];" \
                 : "=r"((r)[0]), "=r"((r)[1]), "=r"((r)[2]), "=r"((r)[3])     \
                 : "r"(addr))

#define MMA_F16(d, a, b)                                                      \
    asm volatile(                                                             \
        "mma.sync.aligned.m16n8k16.row.col.f32.f16.f16.f32 "                  \
        "{%0,%1,%2,%3}, {%4,%5,%6,%7}, {%8,%9}, {%0,%1,%2,%3};\n"             \
        : "+f"((d)[0]), "+f"((d)[1]), "+f"((d)[2]), "+f"((d)[3])              \
        : "r"((a)[0]), "r"((a)[1]), "r"((a)[2]), "r"((a)[3]),                 \
          "r"((b)[0]), "r"((b)[1]))

// ---------------------------------------------------------------------------
// GEMM: C[M,N] = A[M,K] @ B[N,K]^T (+bias), fp32 accum.
// A: single fp16 (m x k). B: fp16 hi/lo (n x k). 2 mma passes: A*Bh + A*Bl.
// ldmatrix fragment loads (mapping proven in R5/R6); 80B rows conflict-free.
// Grid (N/128, M/128, z). EPI: 0 = fp32 out, 2 = fp16 hi/lo split + bias.
// ---------------------------------------------------------------------------
template <int EPI>
__global__ void __launch_bounds__(256) gemm_hl(
    const __half* __restrict__ A, long sA,
    const __half* __restrict__ Bhi, const __half* __restrict__ Blo, long sB,
    const float* __restrict__ bias, int biasStride,
    float* __restrict__ C, __half* __restrict__ Chi, __half* __restrict__ Clo,
    long sC, int K, int ldc)
{
    extern __shared__ __align__(128) char smem[];
    const uint32_t sb0 = s2u(smem);

    const int t = threadIdx.x;
    const int lane = t & 31;
    const int warp = t >> 5;
    const int wm = warp >> 2;            // 0..1 -> 64 rows
    const int wn = warp & 3;             // 0..3 -> 32 cols
    const int bz = blockIdx.z;

    const size_t aBase = (size_t)bz * sA + (size_t)blockIdx.y * 128 * K;
    const size_t bBase = (size_t)bz * sB + (size_t)blockIdx.x * 128 * K;

    // ldmatrix lane constants (x4: lane l supplies row address for matrix l/8)
    const int m4 = lane >> 3;
    const int rA = ((m4 & 1) << 3) + (lane & 7);   // A: m0/m1 rows r,r+8; m2/m3 k+8
    const int kA = (m4 >> 1) << 4;                 // byte offset 0 / 16
    const int rB = ((m4 >> 1) << 3) + (lane & 7);  // B: m0/m1 k halves; m2/m3 n+8
    const int kB = (m4 & 1) << 4;

    auto load_stage = [&](int st, int k0) {
        const uint32_t so = sb0 + st * STAGE_B;
#pragma unroll
        for (int i = 0; i < 2; i++) {
            int id = t + i * 256;            // 512 ids = 128 rows x 4 16B chunks
            int row = id >> 2;
            int c4 = id & 3;
            uint32_t sw = row * RSTRIDE + c4 * 16;
            size_t ga = aBase + (size_t)row * K + k0 + c4 * 8;
            size_t gb = bBase + (size_t)row * K + k0 + c4 * 8;
            cp16(so + sw,              A   + ga);
            cp16(so + TILE_B + sw,     Bhi + gb);
            cp16(so + 2 * TILE_B + sw, Blo + gb);
        }
        asm volatile("cp.async.commit_group;" ::: "memory");
    };

    float acc[4][4][4] = {};
    const int nk = K / KC;
    load_stage(0, 0);

    for (int kt = 0; kt < nk; kt++) {
        if (kt + 1 < nk) {
            load_stage((kt + 1) & 1, (kt + 1) * KC);
            asm volatile("cp.async.wait_group 1;" ::: "memory");
        } else {
            asm volatile("cp.async.wait_group 0;" ::: "memory");
        }
        __syncthreads();

        const uint32_t st = sb0 + (kt & 1) * STAGE_B;
#pragma unroll
        for (int s = 0; s < 2; s++) {            // two k16 steps per chunk
            const int kb = s * 32;               // byte offset within 64B row data
            uint32_t ah[4][4], bh[2][4], bl[2][4];
#pragma unroll
            for (int mi = 0; mi < 4; mi++) {
                int row = wm * 64 + mi * 16 + rA;
                LDSM4(ah[mi], st + row * RSTRIDE + kb + kA);
            }
#pragma unroll
            for (int nt = 0; nt < 2; nt++) {
                int row = wn * 32 + nt * 16 + rB;
                uint32_t ad = st + TILE_B + row * RSTRIDE + kb + kB;
                LDSM4(bh[nt], ad);
                LDSM4(bl[nt], ad + TILE_B);
            }
#pragma unroll
            for (int mi = 0; mi < 4; mi++)
#pragma unroll
                for (int ni = 0; ni < 4; ni++) {
                    const uint32_t* bph = &bh[ni >> 1][(ni & 1) * 2];
                    const uint32_t* bpl = &bl[ni >> 1][(ni & 1) * 2];
                    MMA_F16(acc[mi][ni], ah[mi], bph);
                    MMA_F16(acc[mi][ni], ah[mi], bpl);
                }
        }
        __syncthreads();
    }

    // Epilogue
    const int r = lane >> 2;
    const int cq = lane & 3;
    const int row0 = blockIdx.y * 128 + wm * 64;
    const int col0 = blockIdx.x * 128 + wn * 32;
    const size_t zC = (size_t)bz * sC;

#pragma unroll
    for (int mi = 0; mi < 4; mi++) {
#pragma unroll
        for (int ni = 0; ni < 4; ni++) {
            int rr = row0 + mi * 16 + r;
            int cc = col0 + ni * 8 + 2 * cq;
            if (EPI == 2) {
                float b0 = bias[bz * biasStride + cc];
                float b1 = bias[bz * biasStride + cc + 1];
                __half2 hh, ll;
                h_split2(acc[mi][ni][0] + b0, acc[mi][ni][1] + b1, hh, ll);
                *(__half2*)(Chi + zC + (size_t)rr * ldc + cc) = hh;
                *(__half2*)(Clo + zC + (size_t)rr * ldc + cc) = ll;
                h_split2(acc[mi][ni][2] + b0, acc[mi][ni][3] + b1, hh, ll);
                *(__half2*)(Chi + zC + (size_t)(rr + 8) * ldc + cc) = hh;
                *(__half2*)(Clo + zC + (size_t)(rr + 8) * ldc + cc) = ll;
            } else {
                float* Cp = C + zC;
                float2 v0 = make_float2(acc[mi][ni][0], acc[mi][ni][1]);
                float2 v1 = make_float2(acc[mi][ni][2], acc[mi][ni][3]);
                *(float2*)(Cp + (size_t)rr * ldc + cc) = v0;
                *(float2*)(Cp + (size_t)(rr + 8) * ldc + cc) = v1;
            }
        }
    }
}

// ---------------------------------------------------------------------------
// Batched elementwise convert: 3 fp32 sources -> single fp16
// ---------------------------------------------------------------------------
__global__ void __launch_bounds__(256) cvt3(
    const float* __restrict__ s0, const float* __restrict__ s1,
    const float* __restrict__ s2, __half* __restrict__ dst, int n4each)
{
    const int z = blockIdx.z;
    const float* x = (z == 0) ? s0 : (z == 1) ? s1 : s2;
    int i = blockIdx.x * 256 + threadIdx.x;
    if (i >= n4each) return;
    float4 v = ((const float4*)x)[i];
    __half2 h0, h1;
    h0.x = __float2half(v.x); h0.y = __float2half(v.y);
    h1.x = __float2half(v.z); h1.y = __float2half(v.w);
    size_t base = (size_t)z * n4each * 2;
    ((__half2*)dst)[base + 2 * i]     = h0;
    ((__half2*)dst)[base + 2 * i + 1] = h1;
}

// ---------------------------------------------------------------------------
// Batched split + transpose: W_z[R][C] fp32 -> hi/lo[z][C][R] fp16
// ---------------------------------------------------------------------------
__global__ void __launch_bounds__(256) wsplitT3(
    const float* __restrict__ s0, const float* __restrict__ s1,
    const float* __restrict__ s2, __half* __restrict__ hi,
    __half* __restrict__ lo, int R, int Ccols)
{
    __shared__ float tile[32][33];
    const int z = blockIdx.z;
    const float* xp = (z == 0) ? s0 : (z == 1) ? s1 : s2;
    const size_t zo = (size_t)z * R * Ccols;
    const int c0 = blockIdx.x * 32, r0 = blockIdx.y * 32;
    const int tx = threadIdx.x, ty = threadIdx.y;
#pragma unroll
    for (int i = 0; i < 32; i += 8)
        tile[ty + i][tx] = xp[(size_t)(r0 + ty + i) * Ccols + c0 + tx];
    __syncthreads();
#pragma unroll
    for (int i = 0; i < 32; i += 8) {
        float v = tile[tx][ty + i];
        __half h = __float2half(v);
        __half l = __float2half(v - __half2float(h));
        size_t o = zo + (size_t)(c0 + ty + i) * R + r0 + tx;
        hi[o] = h;
        lo[o] = l;
    }
}

// ---------------------------------------------------------------------------
// fp16 hi+lo transpose: v[z][S][D] -> vt[z][D][S]
// ---------------------------------------------------------------------------
__global__ void __launch_bounds__(256) vtransT(
    const __half* __restrict__ vh, const __half* __restrict__ vl,
    __half* __restrict__ vth, __half* __restrict__ vtl)
{
    __shared__ __half th[32][33], tl[32][33];
    const int z = blockIdx.z;
    const int c0 = blockIdx.x * 32, r0 = blockIdx.y * 32;
    const int tx = threadIdx.x, ty = threadIdx.y;
    const size_t inz = (size_t)z * SEQ * DIM;
#pragma unroll
    for (int i = 0; i < 32; i += 8) {
        size_t o = inz + (size_t)(r0 + ty + i) * DIM + c0 + tx;
        th[ty + i][tx] = vh[o];
        tl[ty + i][tx] = vl[o];
    }
    __syncthreads();
#pragma unroll
    for (int i = 0; i < 32; i += 8) {
        size_t o = inz + (size_t)(c0 + ty + i) * SEQ + r0 + tx;
        vth[o] = th[tx][ty + i];
        vtl[o] = tl[tx][ty + i];
    }
}

// ---------------------------------------------------------------------------
// Row softmax (BETA folded), emits single fp16 probs
// ---------------------------------------------------------------------------
__global__ void __launch_bounds__(256) softmax_h(
    const float* __restrict__ S, __half* __restrict__ P)
{
    __shared__ float red[256];
    const int t = threadIdx.x;
    const size_t base = (size_t)blockIdx.x * SEQ;
    const float* p = S + base;

    float4 v0 = *(const float4*)(p + t * 4);
    float4 v1 = *(const float4*)(p + 1024 + t * 4);
    v0.x *= BETA; v0.y *= BETA; v0.z *= BETA; v0.w *= BETA;
    v1.x *= BETA; v1.y *= BETA; v1.z *= BETA; v1.w *= BETA;

    float m = fmaxf(fmaxf(fmaxf(v0.x, v0.y), fmaxf(v0.z, v0.w)),
                    fmaxf(fmaxf(v1.x, v1.y), fmaxf(v1.z, v1.w)));
    red[t] = m;
    __syncthreads();
    for (int s = 128; s > 0; s >>= 1) {
        if (t < s) red[t] = fmaxf(red[t], red[t + s]);
        __syncthreads();
    }
    m = red[0];
    __syncthreads();

    v0.x = __expf(v0.x - m); v0.y = __expf(v0.y - m);
    v0.z = __expf(v0.z - m); v0.w = __expf(v0.w - m);
    v1.x = __expf(v1.x - m); v1.y = __expf(v1.y - m);
    v1.z = __expf(v1.z - m); v1.w = __expf(v1.w - m);

    float sum = (v0.x + v0.y) + (v0.z + v0.w) + (v1.x + v1.y) + (v1.z + v1.w);
    red[t] = sum;
    __syncthreads();
    for (int s = 128; s > 0; s >>= 1) {
        if (t < s) red[t] += red[t + s];
        __syncthreads();
    }
    const float inv = 1.0f / red[0];

    __half2 o0, o1, o2, o3;
    o0.x = __float2half(v0.x * inv); o0.y = __float2half(v0.y * inv);
    o1.x = __float2half(v0.z * inv); o1.y = __float2half(v0.w * inv);
    o2.x = __float2half(v1.x * inv); o2.y = __float2half(v1.y * inv);
    o3.x = __float2half(v1.z * inv); o3.y = __float2half(v1.w * inv);
    *(__half2*)(P + base + t * 4)        = o0;
    *(__half2*)(P + base + t * 4 + 2)    = o1;
    *(__half2*)(P + base + 1024 + t * 4)     = o2;
    *(__half2*)(P + base + 1024 + t * 4 + 2) = o3;
}

// ---------------------------------------------------------------------------
// Launch
// ---------------------------------------------------------------------------
extern "C" void kernel_launch(void* const* d_in, const int* in_sizes, int n_in,
                              void* d_out, int out_size)
{
    const float* query = (const float*)d_in[0];
    const float* key   = (const float*)d_in[1];
    const float* value = (const float*)d_in[2];
    const float* Wq    = (const float*)d_in[3];
    const float* bq    = (const float*)d_in[4];
    const float* Wk    = (const float*)d_in[5];
    const float* bk    = (const float*)d_in[6];
    const float* Wv    = (const float*)d_in[7];
    const float* bv    = (const float*)d_in[8];
    float* out = (float*)d_out;

    __half *x, *wh, *wl, *qkvh, *qkvl, *vth, *vtl, *pp;
    float *sf, *bias;
    cudaGetSymbolAddress((void**)&x, g_x);
    cudaGetSymbolAddress((void**)&wh, g_wh);
    cudaGetSymbolAddress((void**)&wl, g_wl);
    cudaGetSymbolAddress((void**)&bias, g_bias);
    cudaGetSymbolAddress((void**)&qkvh, g_qkvh);
    cudaGetSymbolAddress((void**)&qkvl, g_qkvl);
    cudaGetSymbolAddress((void**)&vth, g_vth);
    cudaGetSymbolAddress((void**)&vtl, g_vtl);
    cudaGetSymbolAddress((void**)&sf, g_sf);
    cudaGetSymbolAddress((void**)&pp, g_p);

    cudaFuncSetAttribute((const void*)gemm_hl<0>,
                         cudaFuncAttributeMaxDynamicSharedMemorySize, SMEM_TOTAL);
    cudaFuncSetAttribute((const void*)gemm_hl<2>,
                         cudaFuncAttributeMaxDynamicSharedMemorySize, SMEM_TOTAL);

    const long PD = (long)MTOT * DIM;     // per-z projection stride
    const int nIn4 = MTOT * DIM / 4;

    // ---- Gather biases (capturable D2D async copies) ----
    cudaMemcpyAsync(bias,           bq, DIM * sizeof(float), cudaMemcpyDeviceToDevice);
    cudaMemcpyAsync(bias + DIM,     bk, DIM * sizeof(float), cudaMemcpyDeviceToDevice);
    cudaMemcpyAsync(bias + 2 * DIM, bv, DIM * sizeof(float), cudaMemcpyDeviceToDevice);

    // ---- Inputs -> fp16 single; weights -> fp16 hi/lo transposed ----
    cvt3<<<dim3(nIn4 / 256, 1, 3), 256>>>(query, key, value, x, nIn4);
    wsplitT3<<<dim3(DIM / 32, DIM / 32, 3), dim3(32, 8)>>>(Wq, Wk, Wv, wh, wl, DIM, DIM);

    // ---- Batched projections (z=3): A = x single, B = W hi/lo ----
    gemm_hl<2><<<dim3(DIM / 128, MTOT / 128, 3), 256, SMEM_TOTAL>>>(
        x, PD, wh, wl, (long)DIM * DIM, bias, DIM,
        nullptr, qkvh, qkvl, PD, DIM, DIM);

    // ---- Transpose V (hi/lo) to [z][D][S] ----
    vtransT<<<dim3(DIM / 32, SEQ / 32, BATCH), dim3(32, 8)>>>(
        qkvh + 2 * PD, qkvl + 2 * PD, vth, vtl);

    // ---- Scores: A = q_hi (fp16(q), unsplit), B = k hi/lo ----
    gemm_hl<0><<<dim3(SEQ / 128, SEQ / 128, BATCH), 256, SMEM_TOTAL>>>(
        qkvh, (long)SEQ * DIM, qkvh + PD, qkvl + PD, (long)SEQ * DIM,
        nullptr, 0, sf, nullptr, nullptr, (long)SEQ * SEQ, DIM, SEQ);

    // ---- Softmax (beta folded) -> fp16 probs ----
    softmax_h<<<BATCH * SEQ, 256>>>(sf, pp);

    // ---- Out: A = probs (unsplit), B = v^T hi/lo ----
    gemm_hl<0><<<dim3(DIM / 128, SEQ / 128, BATCH), 256, SMEM_TOTAL>>>(
        pp, (long)SEQ * SEQ, vth, vtl, (long)SEQ * DIM,
        nullptr, 0, out, nullptr, nullptr, (long)SEQ * DIM, SEQ, DIM);
}

// round 9
// speedup vs baseline: 2.3774x; 1.5133x over previous
#include <cuda_runtime.h>
#include <cuda_fp16.h>
#include <stdint.h>
#include <math.h>

// Problem constants
#define BATCH 4
#define SEQ   2048
#define DIM   1024
#define MTOT  (BATCH * SEQ)      // 8192
#define BETA  0.03125f

// GEMM tiling: 128x128 CTA tile, K-chunk 32, 80B padded rows (proven config)
#define KC       32
#define RSTRIDE  80                  // bytes per smem row (32 fp16 + 16B pad)
#define TILE_B   (128 * RSTRIDE)     // 10240 B
#define STAGE_B  (2 * TILE_B)        // A | B = 20480 B
#define SMEM_TOTAL (2 * STAGE_B)     // 40960 B, 2 stages

// ---------------------------------------------------------------------------
// Scratch (__device__ globals; allocation-free rule)
// ---------------------------------------------------------------------------
__device__ __align__(16) __half g_x[3 * MTOT * DIM];      // fp16 inputs
__device__ __align__(16) __half g_w[3 * DIM * DIM];       // fp16 weights (transposed)
__device__ __align__(16) float  g_bias[3 * DIM];
__device__ __align__(16) __half g_qkv[3 * MTOT * DIM];    // fp16 q,k,v
__device__ __align__(16) __half g_vt[MTOT * DIM];         // v transposed [z][D][S]
__device__ __align__(16) float  g_sf[(size_t)BATCH * SEQ * SEQ];
__device__ __align__(16) __half g_p[(size_t)BATCH * SEQ * SEQ];  // probs

// ---------------------------------------------------------------------------
// Helpers
// ---------------------------------------------------------------------------
__device__ __forceinline__ uint32_t s2u(const void* p) {
    return (uint32_t)__cvta_generic_to_shared(p);
}
__device__ __forceinline__ void cp16(uint32_t s, const void* g) {
    asm volatile("cp.async.cg.shared.global [%0], [%1], 16;" :: "r"(s), "l"(g));
}

#define LDSM4(r, addr)                                                        \
    asm volatile("ldmatrix.sync.aligned.m8n8.x4.shared.b16 {%0,%1,%2,%3}, [%4];" \
                 : "=r"((r)[0]), "=r"((r)[1]), "=r"((r)[2]), "=r"((r)[3])     \
                 : "r"(addr))

#define MMA_F16(d, a, b)                                                      \
    asm volatile(                                                             \
        "mma.sync.aligned.m16n8k16.row.col.f32.f16.f16.f32 "                  \
        "{%0,%1,%2,%3}, {%4,%5,%6,%7}, {%8,%9}, {%0,%1,%2,%3};\n"             \
        : "+f"((d)[0]), "+f"((d)[1]), "+f"((d)[2]), "+f"((d)[3])              \
        : "r"((a)[0]), "r"((a)[1]), "r"((a)[2]), "r"((a)[3]),                 \
          "r"((b)[0]), "r"((b)[1]))

// ---------------------------------------------------------------------------
// GEMM: C[M,N] = A[M,K] @ B[N,K]^T (+bias), fp32 accum, single-pass fp16.
// ldmatrix fragments (proven mapping); 80B rows conflict-free for LDSM.
// Grid (N/128, M/128, z). EPI: 0 = fp32 out, 2 = fp16 out + bias.
// ---------------------------------------------------------------------------
template <int EPI>
__global__ void __launch_bounds__(256) gemm_s(
    const __half* __restrict__ A, long sA,
    const __half* __restrict__ B, long sB,
    const float* __restrict__ bias, int biasStride,
    float* __restrict__ C, __half* __restrict__ Ch,
    long sC, int K, int ldc)
{
    extern __shared__ __align__(128) char smem[];
    const uint32_t sb0 = s2u(smem);

    const int t = threadIdx.x;
    const int lane = t & 31;
    const int warp = t >> 5;
    const int wm = warp >> 2;            // 0..1 -> 64 rows
    const int wn = warp & 3;             // 0..3 -> 32 cols
    const int bz = blockIdx.z;

    const size_t aBase = (size_t)bz * sA + (size_t)blockIdx.y * 128 * K;
    const size_t bBase = (size_t)bz * sB + (size_t)blockIdx.x * 128 * K;

    // ldmatrix lane constants (x4: lane l supplies row address for matrix l/8)
    const int m4 = lane >> 3;
    const int rA = ((m4 & 1) << 3) + (lane & 7);   // A: m0/m1 rows r,r+8; m2/m3 k+8
    const int kA = (m4 >> 1) << 4;                 // byte offset 0 / 16
    const int rB = ((m4 >> 1) << 3) + (lane & 7);  // B: m0/m1 k halves; m2/m3 n+8
    const int kB = (m4 & 1) << 4;

    auto load_stage = [&](int st, int k0) {
        const uint32_t so = sb0 + st * STAGE_B;
#pragma unroll
        for (int i = 0; i < 2; i++) {
            int id = t + i * 256;            // 512 ids = 128 rows x 4 16B chunks
            int row = id >> 2;
            int c4 = id & 3;
            uint32_t sw = row * RSTRIDE + c4 * 16;
            size_t ga = aBase + (size_t)row * K + k0 + c4 * 8;
            size_t gb = bBase + (size_t)row * K + k0 + c4 * 8;
            cp16(so + sw,          A + ga);
            cp16(so + TILE_B + sw, B + gb);
        }
        asm volatile("cp.async.commit_group;" ::: "memory");
    };

    float acc[4][4][4] = {};
    const int nk = K / KC;
    load_stage(0, 0);

    for (int kt = 0; kt < nk; kt++) {
        if (kt + 1 < nk) {
            load_stage((kt + 1) & 1, (kt + 1) * KC);
            asm volatile("cp.async.wait_group 1;" ::: "memory");
        } else {
            asm volatile("cp.async.wait_group 0;" ::: "memory");
        }
        __syncthreads();

        const uint32_t st = sb0 + (kt & 1) * STAGE_B;
#pragma unroll
        for (int s = 0; s < 2; s++) {            // two k16 steps per chunk
            const int kb = s * 32;               // byte offset within 64B row data
            uint32_t ah[4][4], bh[2][4];
#pragma unroll
            for (int mi = 0; mi < 4; mi++) {
                int row = wm * 64 + mi * 16 + rA;
                LDSM4(ah[mi], st + row * RSTRIDE + kb + kA);
            }
#pragma unroll
            for (int nt = 0; nt < 2; nt++) {
                int row = wn * 32 + nt * 16 + rB;
                LDSM4(bh[nt], st + TILE_B + row * RSTRIDE + kb + kB);
            }
#pragma unroll
            for (int mi = 0; mi < 4; mi++)
#pragma unroll
                for (int ni = 0; ni < 4; ni++) {
                    const uint32_t* bp = &bh[ni >> 1][(ni & 1) * 2];
                    MMA_F16(acc[mi][ni], ah[mi], bp);
                }
        }
        __syncthreads();
    }

    // Epilogue
    const int r = lane >> 2;
    const int cq = lane & 3;
    const int row0 = blockIdx.y * 128 + wm * 64;
    const int col0 = blockIdx.x * 128 + wn * 32;
    const size_t zC = (size_t)bz * sC;

#pragma unroll
    for (int mi = 0; mi < 4; mi++) {
#pragma unroll
        for (int ni = 0; ni < 4; ni++) {
            int rr = row0 + mi * 16 + r;
            int cc = col0 + ni * 8 + 2 * cq;
            if (EPI == 2) {
                float b0 = bias[bz * biasStride + cc];
                float b1 = bias[bz * biasStride + cc + 1];
                __half2 h0, h1;
                h0.x = __float2half(acc[mi][ni][0] + b0);
                h0.y = __float2half(acc[mi][ni][1] + b1);
                h1.x = __float2half(acc[mi][ni][2] + b0);
                h1.y = __float2half(acc[mi][ni][3] + b1);
                *(__half2*)(Ch + zC + (size_t)rr * ldc + cc) = h0;
                *(__half2*)(Ch + zC + (size_t)(rr + 8) * ldc + cc) = h1;
            } else {
                float* Cp = C + zC;
                float2 v0 = make_float2(acc[mi][ni][0], acc[mi][ni][1]);
                float2 v1 = make_float2(acc[mi][ni][2], acc[mi][ni][3]);
                *(float2*)(Cp + (size_t)rr * ldc + cc) = v0;
                *(float2*)(Cp + (size_t)(rr + 8) * ldc + cc) = v1;
            }
        }
    }
}

// ---------------------------------------------------------------------------
// Batched elementwise convert: 3 fp32 sources -> fp16
// ---------------------------------------------------------------------------
__global__ void __launch_bounds__(256) cvt3(
    const float* __restrict__ s0, const float* __restrict__ s1,
    const float* __restrict__ s2, __half* __restrict__ dst, int n4each)
{
    const int z = blockIdx.z;
    const float* x = (z == 0) ? s0 : (z == 1) ? s1 : s2;
    int i = blockIdx.x * 256 + threadIdx.x;
    if (i >= n4each) return;
    float4 v = ((const float4*)x)[i];
    __half2 h0, h1;
    h0.x = __float2half(v.x); h0.y = __float2half(v.y);
    h1.x = __float2half(v.z); h1.y = __float2half(v.w);
    size_t base = (size_t)z * n4each * 2;
    ((__half2*)dst)[base + 2 * i]     = h0;
    ((__half2*)dst)[base + 2 * i + 1] = h1;
}

// ---------------------------------------------------------------------------
// Batched convert + transpose: W_z[R][C] fp32 -> fp16 [z][C][R]
// ---------------------------------------------------------------------------
__global__ void __launch_bounds__(256) wcvtT3(
    const float* __restrict__ s0, const float* __restrict__ s1,
    const float* __restrict__ s2, __half* __restrict__ dst, int R, int Ccols)
{
    __shared__ float tile[32][33];
    const int z = blockIdx.z;
    const float* xp = (z == 0) ? s0 : (z == 1) ? s1 : s2;
    const size_t zo = (size_t)z * R * Ccols;
    const int c0 = blockIdx.x * 32, r0 = blockIdx.y * 32;
    const int tx = threadIdx.x, ty = threadIdx.y;
#pragma unroll
    for (int i = 0; i < 32; i += 8)
        tile[ty + i][tx] = xp[(size_t)(r0 + ty + i) * Ccols + c0 + tx];
    __syncthreads();
#pragma unroll
    for (int i = 0; i < 32; i += 8) {
        size_t o = zo + (size_t)(c0 + ty + i) * R + r0 + tx;
        dst[o] = __float2half(tile[tx][ty + i]);
    }
}

// ---------------------------------------------------------------------------
// fp16 transpose: v[z][S][D] -> vt[z][D][S]
// ---------------------------------------------------------------------------
__global__ void __launch_bounds__(256) vtransT(
    const __half* __restrict__ v, __half* __restrict__ vt)
{
    __shared__ __half th[32][33];
    const int z = blockIdx.z;
    const int c0 = blockIdx.x * 32, r0 = blockIdx.y * 32;
    const int tx = threadIdx.x, ty = threadIdx.y;
    const size_t inz = (size_t)z * SEQ * DIM;
#pragma unroll
    for (int i = 0; i < 32; i += 8)
        th[ty + i][tx] = v[inz + (size_t)(r0 + ty + i) * DIM + c0 + tx];
    __syncthreads();
#pragma unroll
    for (int i = 0; i < 32; i += 8)
        vt[inz + (size_t)(c0 + ty + i) * SEQ + r0 + tx] = th[tx][ty + i];
}

// ---------------------------------------------------------------------------
// Row softmax (BETA folded), emits fp16 probs
// ---------------------------------------------------------------------------
__global__ void __launch_bounds__(256) softmax_h(
    const float* __restrict__ S, __half* __restrict__ P)
{
    __shared__ float red[256];
    const int t = threadIdx.x;
    const size_t base = (size_t)blockIdx.x * SEQ;
    const float* p = S + base;

    float4 v0 = *(const float4*)(p + t * 4);
    float4 v1 = *(const float4*)(p + 1024 + t * 4);
    v0.x *= BETA; v0.y *= BETA; v0.z *= BETA; v0.w *= BETA;
    v1.x *= BETA; v1.y *= BETA; v1.z *= BETA; v1.w *= BETA;

    float m = fmaxf(fmaxf(fmaxf(v0.x, v0.y), fmaxf(v0.z, v0.w)),
                    fmaxf(fmaxf(v1.x, v1.y), fmaxf(v1.z, v1.w)));
    red[t] = m;
    __syncthreads();
    for (int s = 128; s > 0; s >>= 1) {
        if (t < s) red[t] = fmaxf(red[t], red[t + s]);
        __syncthreads();
    }
    m = red[0];
    __syncthreads();

    v0.x = __expf(v0.x - m); v0.y = __expf(v0.y - m);
    v0.z = __expf(v0.z - m); v0.w = __expf(v0.w - m);
    v1.x = __expf(v1.x - m); v1.y = __expf(v1.y - m);
    v1.z = __expf(v1.z - m); v1.w = __expf(v1.w - m);

    float sum = (v0.x + v0.y) + (v0.z + v0.w) + (v1.x + v1.y) + (v1.z + v1.w);
    red[t] = sum;
    __syncthreads();
    for (int s = 128; s > 0; s >>= 1) {
        if (t < s) red[t] += red[t + s];
        __syncthreads();
    }
    const float inv = 1.0f / red[0];

    __half2 o0, o1, o2, o3;
    o0.x = __float2half(v0.x * inv); o0.y = __float2half(v0.y * inv);
    o1.x = __float2half(v0.z * inv); o1.y = __float2half(v0.w * inv);
    o2.x = __float2half(v1.x * inv); o2.y = __float2half(v1.y * inv);
    o3.x = __float2half(v1.z * inv); o3.y = __float2half(v1.w * inv);
    *(__half2*)(P + base + t * 4)        = o0;
    *(__half2*)(P + base + t * 4 + 2)    = o1;
    *(__half2*)(P + base + 1024 + t * 4)     = o2;
    *(__half2*)(P + base + 1024 + t * 4 + 2) = o3;
}

// ---------------------------------------------------------------------------
// Launch
// ---------------------------------------------------------------------------
extern "C" void kernel_launch(void* const* d_in, const int* in_sizes, int n_in,
                              void* d_out, int out_size)
{
    const float* query = (const float*)d_in[0];
    const float* key   = (const float*)d_in[1];
    const float* value = (const float*)d_in[2];
    const float* Wq    = (const float*)d_in[3];
    const float* bq    = (const float*)d_in[4];
    const float* Wk    = (const float*)d_in[5];
    const float* bk    = (const float*)d_in[6];
    const float* Wv    = (const float*)d_in[7];
    const float* bv    = (const float*)d_in[8];
    float* out = (float*)d_out;

    __half *x, *w, *qkv, *vt, *pp;
    float *sf, *bias;
    cudaGetSymbolAddress((void**)&x, g_x);
    cudaGetSymbolAddress((void**)&w, g_w);
    cudaGetSymbolAddress((void**)&bias, g_bias);
    cudaGetSymbolAddress((void**)&qkv, g_qkv);
    cudaGetSymbolAddress((void**)&vt, g_vt);
    cudaGetSymbolAddress((void**)&sf, g_sf);
    cudaGetSymbolAddress((void**)&pp, g_p);

    cudaFuncSetAttribute((const void*)gemm_s<0>,
                         cudaFuncAttributeMaxDynamicSharedMemorySize, SMEM_TOTAL);
    cudaFuncSetAttribute((const void*)gemm_s<2>,
                         cudaFuncAttributeMaxDynamicSharedMemorySize, SMEM_TOTAL);

    const long PD = (long)MTOT * DIM;     // per-z projection stride
    const int nIn4 = MTOT * DIM / 4;

    // ---- Gather biases (capturable D2D async copies) ----
    cudaMemcpyAsync(bias,           bq, DIM * sizeof(float), cudaMemcpyDeviceToDevice);
    cudaMemcpyAsync(bias + DIM,     bk, DIM * sizeof(float), cudaMemcpyDeviceToDevice);
    cudaMemcpyAsync(bias + 2 * DIM, bv, DIM * sizeof(float), cudaMemcpyDeviceToDevice);

    // ---- Inputs -> fp16; weights -> fp16 transposed ----
    cvt3<<<dim3(nIn4 / 256, 1, 3), 256>>>(query, key, value, x, nIn4);
    wcvtT3<<<dim3(DIM / 32, DIM / 32, 3), dim3(32, 8)>>>(Wq, Wk, Wv, w, DIM, DIM);

    // ---- Batched projections (z=3), fp16 out + bias ----
    gemm_s<2><<<dim3(DIM / 128, MTOT / 128, 3), 256, SMEM_TOTAL>>>(
        x, PD, w, (long)DIM * DIM, bias, DIM,
        nullptr, qkv, PD, DIM, DIM);

    // ---- Transpose V to [z][D][S] ----
    vtransT<<<dim3(DIM / 32, SEQ / 32, BATCH), dim3(32, 8)>>>(qkv + 2 * PD, vt);

    // ---- Scores: q @ k^T (fp32 out) ----
    gemm_s<0><<<dim3(SEQ / 128, SEQ / 128, BATCH), 256, SMEM_TOTAL>>>(
        qkv, (long)SEQ * DIM, qkv + PD, (long)SEQ * DIM,
        nullptr, 0, sf, nullptr, (long)SEQ * SEQ, DIM, SEQ);

    // ---- Softmax (beta folded) -> fp16 probs ----
    softmax_h<<<BATCH * SEQ, 256>>>(sf, pp);

    // ---- Out: probs @ v^T ----
    gemm_s<0><<<dim3(DIM / 128, SEQ / 128, BATCH), 256, SMEM_TOTAL>>>(
        pp, (long)SEQ * SEQ, vt, (long)SEQ * DIM,
        nullptr, 0, out, nullptr, (long)SEQ * DIM, SEQ, DIM);
}

// round 10
// speedup vs baseline: 2.7878x; 1.1726x over previous
#include <cuda_runtime.h>
#include <cuda_fp16.h>
#include <stdint.h>
#include <math.h>

// Problem constants
#define BATCH 4
#define SEQ   2048
#define DIM   1024
#define MTOT  (BATCH * SEQ)      // 8192
#define BETA  0.03125f
#define BLOG2E 0.04508422f       // BETA * log2(e)

// GEMM tiling: 128x128 CTA tile, K-chunk 32, 80B padded rows, 3-stage pipeline
#define KC       32
#define RSTRIDE  80                  // bytes per smem row (32 fp16 + 16B pad)
#define TILE_B   (128 * RSTRIDE)     // 10240 B
#define STAGE_B  (2 * TILE_B)        // A | B = 20480 B
#define NSTAGE   3
#define SMEM_TOTAL (NSTAGE * STAGE_B)  // 61440 B -> 2 CTAs/SM

// ---------------------------------------------------------------------------
// Scratch (__device__ globals; allocation-free rule)
// ---------------------------------------------------------------------------
__device__ __align__(16) __half g_x[3 * MTOT * DIM];      // fp16 inputs
__device__ __align__(16) __half g_w[3 * DIM * DIM];       // fp16 weights (transposed)
__device__ __align__(16) float  g_bias[3 * DIM];
__device__ __align__(16) __half g_qkv[3 * MTOT * DIM];    // fp16 q,k,v
__device__ __align__(16) __half g_vt[MTOT * DIM];         // v transposed [z][D][S]
__device__ __align__(16) __half g_p[(size_t)BATCH * SEQ * SEQ];  // exp(beta*s), unnormalized
__device__ __align__(16) float  g_rinv[MTOT];             // 1 / rowsum

// ---------------------------------------------------------------------------
// Helpers
// ---------------------------------------------------------------------------
__device__ __forceinline__ uint32_t s2u(const void* p) {
    return (uint32_t)__cvta_generic_to_shared(p);
}
__device__ __forceinline__ void cp16(uint32_t s, const void* g) {
    asm volatile("cp.async.cg.shared.global [%0], [%1], 16;" :: "r"(s), "l"(g));
}

#define LDSM4(r, addr)                                                        \
    asm volatile("ldmatrix.sync.aligned.m8n8.x4.shared.b16 {%0,%1,%2,%3}, [%4];" \
                 : "=r"((r)[0]), "=r"((r)[1]), "=r"((r)[2]), "=r"((r)[3])     \
                 : "r"(addr))

#define MMA_F16(d, a, b)                                                      \
    asm volatile(                                                             \
        "mma.sync.aligned.m16n8k16.row.col.f32.f16.f16.f32 "                  \
        "{%0,%1,%2,%3}, {%4,%5,%6,%7}, {%8,%9}, {%0,%1,%2,%3};\n"             \
        : "+f"((d)[0]), "+f"((d)[1]), "+f"((d)[2]), "+f"((d)[3])              \
        : "r"((a)[0]), "r"((a)[1]), "r"((a)[2]), "r"((a)[3]),                 \
          "r"((b)[0]), "r"((b)[1]))

// ---------------------------------------------------------------------------
// GEMM: C[M,N] = A[M,K] @ B[N,K]^T, fp32 accum, single-pass fp16, 3-stage.
// EPI: 2 = fp16 out + bias (projections)
//      3 = fp16 exp(BETA * acc) (scores -> unnormalized probs)
//      4 = fp32 out * rinv[row]  (AV -> final output)
// Grid (N/128, M/128, z).
// ---------------------------------------------------------------------------
template <int EPI>
__global__ void __launch_bounds__(256) gemm_s(
    const __half* __restrict__ A, long sA,
    const __half* __restrict__ B, long sB,
    const float* __restrict__ bias, int biasStride,
    const float* __restrict__ rinv,
    float* __restrict__ C, __half* __restrict__ Ch,
    long sC, int K, int ldc)
{
    extern __shared__ __align__(128) char smem[];
    const uint32_t sb0 = s2u(smem);

    const int t = threadIdx.x;
    const int lane = t & 31;
    const int warp = t >> 5;
    const int wm = warp >> 2;            // 0..1 -> 64 rows
    const int wn = warp & 3;             // 0..3 -> 32 cols
    const int bz = blockIdx.z;

    const size_t aBase = (size_t)bz * sA + (size_t)blockIdx.y * 128 * K;
    const size_t bBase = (size_t)bz * sB + (size_t)blockIdx.x * 128 * K;

    // ldmatrix lane constants (proven mapping)
    const int m4 = lane >> 3;
    const int rA = ((m4 & 1) << 3) + (lane & 7);
    const int kA = (m4 >> 1) << 4;
    const int rB = ((m4 >> 1) << 3) + (lane & 7);
    const int kB = (m4 & 1) << 4;

    auto load_stage = [&](int st, int k0) {
        const uint32_t so = sb0 + st * STAGE_B;
#pragma unroll
        for (int i = 0; i < 2; i++) {
            int id = t + i * 256;            // 512 ids = 128 rows x 4 16B chunks
            int row = id >> 2;
            int c4 = id & 3;
            uint32_t sw = row * RSTRIDE + c4 * 16;
            size_t ga = aBase + (size_t)row * K + k0 + c4 * 8;
            size_t gb = bBase + (size_t)row * K + k0 + c4 * 8;
            cp16(so + sw,          A + ga);
            cp16(so + TILE_B + sw, B + gb);
        }
        asm volatile("cp.async.commit_group;" ::: "memory");
    };

    float acc[4][4][4] = {};
    const int nk = K / KC;
    load_stage(0, 0);
    load_stage(1, KC);

    for (int kt = 0; kt < nk; kt++) {
        // stage kt's group done when <=1 outstanding (only kt+1 may remain)
        asm volatile("cp.async.wait_group 1;" ::: "memory");
        __syncthreads();
        if (kt + 2 < nk) load_stage((kt + 2) % NSTAGE, (kt + 2) * KC);

        const uint32_t st = sb0 + (kt % NSTAGE) * STAGE_B;
#pragma unroll
        for (int s = 0; s < 2; s++) {            // two k16 steps per chunk
            const int kb = s * 32;
            uint32_t ah[4][4], bh[2][4];
#pragma unroll
            for (int mi = 0; mi < 4; mi++) {
                int row = wm * 64 + mi * 16 + rA;
                LDSM4(ah[mi], st + row * RSTRIDE + kb + kA);
            }
#pragma unroll
            for (int nt = 0; nt < 2; nt++) {
                int row = wn * 32 + nt * 16 + rB;
                LDSM4(bh[nt], st + TILE_B + row * RSTRIDE + kb + kB);
            }
#pragma unroll
            for (int mi = 0; mi < 4; mi++)
#pragma unroll
                for (int ni = 0; ni < 4; ni++) {
                    const uint32_t* bp = &bh[ni >> 1][(ni & 1) * 2];
                    MMA_F16(acc[mi][ni], ah[mi], bp);
                }
        }
    }

    // Epilogue
    const int r = lane >> 2;
    const int cq = lane & 3;
    const int row0 = blockIdx.y * 128 + wm * 64;
    const int col0 = blockIdx.x * 128 + wn * 32;
    const size_t zC = (size_t)bz * sC;

#pragma unroll
    for (int mi = 0; mi < 4; mi++) {
#pragma unroll
        for (int ni = 0; ni < 4; ni++) {
            int rr = row0 + mi * 16 + r;
            int cc = col0 + ni * 8 + 2 * cq;
            if (EPI == 2) {
                float b0 = bias[bz * biasStride + cc];
                float b1 = bias[bz * biasStride + cc + 1];
                __half2 h0, h1;
                h0.x = __float2half(acc[mi][ni][0] + b0);
                h0.y = __float2half(acc[mi][ni][1] + b1);
                h1.x = __float2half(acc[mi][ni][2] + b0);
                h1.y = __float2half(acc[mi][ni][3] + b1);
                *(__half2*)(Ch + zC + (size_t)rr * ldc + cc) = h0;
                *(__half2*)(Ch + zC + (size_t)(rr + 8) * ldc + cc) = h1;
            } else if (EPI == 3) {
                __half2 h0, h1;
                h0.x = __float2half(exp2f(acc[mi][ni][0] * BLOG2E));
                h0.y = __float2half(exp2f(acc[mi][ni][1] * BLOG2E));
                h1.x = __float2half(exp2f(acc[mi][ni][2] * BLOG2E));
                h1.y = __float2half(exp2f(acc[mi][ni][3] * BLOG2E));
                *(__half2*)(Ch + zC + (size_t)rr * ldc + cc) = h0;
                *(__half2*)(Ch + zC + (size_t)(rr + 8) * ldc + cc) = h1;
            } else {  // EPI == 4
                float inv0 = rinv[bz * SEQ + rr];
                float inv1 = rinv[bz * SEQ + rr + 8];
                float* Cp = C + zC;
                float2 v0 = make_float2(acc[mi][ni][0] * inv0, acc[mi][ni][1] * inv0);
                float2 v1 = make_float2(acc[mi][ni][2] * inv1, acc[mi][ni][3] * inv1);
                *(float2*)(Cp + (size_t)rr * ldc + cc) = v0;
                *(float2*)(Cp + (size_t)(rr + 8) * ldc + cc) = v1;
            }
        }
    }
}

// ---------------------------------------------------------------------------
// Row reciprocal-sum: rinv[row] = 1 / sum(P[row, :])   (P fp16, SEQ cols)
// ---------------------------------------------------------------------------
__global__ void __launch_bounds__(256) rowsum_inv(
    const __half* __restrict__ P, float* __restrict__ rinv)
{
    __shared__ float red[256];
    const int t = threadIdx.x;
    const __half2* p2 = (const __half2*)(P + (size_t)blockIdx.x * SEQ);
    float s = 0.f;
#pragma unroll
    for (int j = 0; j < 4; j++) {
        float2 v = __half22float2(p2[t * 4 + j]);
        s += v.x + v.y;
    }
    red[t] = s;
    __syncthreads();
    for (int k = 128; k > 0; k >>= 1) {
        if (t < k) red[t] += red[t + k];
        __syncthreads();
    }
    if (t == 0) rinv[blockIdx.x] = 1.0f / red[0];
}

// ---------------------------------------------------------------------------
// Batched elementwise convert: 3 fp32 sources -> fp16
// ---------------------------------------------------------------------------
__global__ void __launch_bounds__(256) cvt3(
    const float* __restrict__ s0, const float* __restrict__ s1,
    const float* __restrict__ s2, __half* __restrict__ dst, int n4each)
{
    const int z = blockIdx.z;
    const float* x = (z == 0) ? s0 : (z == 1) ? s1 : s2;
    int i = blockIdx.x * 256 + threadIdx.x;
    if (i >= n4each) return;
    float4 v = ((const float4*)x)[i];
    __half2 h0, h1;
    h0.x = __float2half(v.x); h0.y = __float2half(v.y);
    h1.x = __float2half(v.z); h1.y = __float2half(v.w);
    size_t base = (size_t)z * n4each * 2;
    ((__half2*)dst)[base + 2 * i]     = h0;
    ((__half2*)dst)[base + 2 * i + 1] = h1;
}

// ---------------------------------------------------------------------------
// Batched convert + transpose: W_z[R][C] fp32 -> fp16 [z][C][R]
// ---------------------------------------------------------------------------
__global__ void __launch_bounds__(256) wcvtT3(
    const float* __restrict__ s0, const float* __restrict__ s1,
    const float* __restrict__ s2, __half* __restrict__ dst, int R, int Ccols)
{
    __shared__ float tile[32][33];
    const int z = blockIdx.z;
    const float* xp = (z == 0) ? s0 : (z == 1) ? s1 : s2;
    const size_t zo = (size_t)z * R * Ccols;
    const int c0 = blockIdx.x * 32, r0 = blockIdx.y * 32;
    const int tx = threadIdx.x, ty = threadIdx.y;
#pragma unroll
    for (int i = 0; i < 32; i += 8)
        tile[ty + i][tx] = xp[(size_t)(r0 + ty + i) * Ccols + c0 + tx];
    __syncthreads();
#pragma unroll
    for (int i = 0; i < 32; i += 8) {
        size_t o = zo + (size_t)(c0 + ty + i) * R + r0 + tx;
        dst[o] = __float2half(tile[tx][ty + i]);
    }
}

// ---------------------------------------------------------------------------
// fp16 transpose: v[z][S][D] -> vt[z][D][S]
// ---------------------------------------------------------------------------
__global__ void __launch_bounds__(256) vtransT(
    const __half* __restrict__ v, __half* __restrict__ vt)
{
    __shared__ __half th[32][33];
    const int z = blockIdx.z;
    const int c0 = blockIdx.x * 32, r0 = blockIdx.y * 32;
    const int tx = threadIdx.x, ty = threadIdx.y;
    const size_t inz = (size_t)z * SEQ * DIM;
#pragma unroll
    for (int i = 0; i < 32; i += 8)
        th[ty + i][tx] = v[inz + (size_t)(r0 + ty + i) * DIM + c0 + tx];
    __syncthreads();
#pragma unroll
    for (int i = 0; i < 32; i += 8)
        vt[inz + (size_t)(c0 + ty + i) * SEQ + r0 + tx] = th[tx][ty + i];
}

// ---------------------------------------------------------------------------
// Launch
// ---------------------------------------------------------------------------
extern "C" void kernel_launch(void* const* d_in, const int* in_sizes, int n_in,
                              void* d_out, int out_size)
{
    const float* query = (const float*)d_in[0];
    const float* key   = (const float*)d_in[1];
    const float* value = (const float*)d_in[2];
    const float* Wq    = (const float*)d_in[3];
    const float* bq    = (const float*)d_in[4];
    const float* Wk    = (const float*)d_in[5];
    const float* bk    = (const float*)d_in[6];
    const float* Wv    = (const float*)d_in[7];
    const float* bv    = (const float*)d_in[8];
    float* out = (float*)d_out;

    __half *x, *w, *qkv, *vt, *pp;
    float *bias, *rinv;
    cudaGetSymbolAddress((void**)&x, g_x);
    cudaGetSymbolAddress((void**)&w, g_w);
    cudaGetSymbolAddress((void**)&bias, g_bias);
    cudaGetSymbolAddress((void**)&qkv, g_qkv);
    cudaGetSymbolAddress((void**)&vt, g_vt);
    cudaGetSymbolAddress((void**)&pp, g_p);
    cudaGetSymbolAddress((void**)&rinv, g_rinv);

    cudaFuncSetAttribute((const void*)gemm_s<2>,
                         cudaFuncAttributeMaxDynamicSharedMemorySize, SMEM_TOTAL);
    cudaFuncSetAttribute((const void*)gemm_s<3>,
                         cudaFuncAttributeMaxDynamicSharedMemorySize, SMEM_TOTAL);
    cudaFuncSetAttribute((const void*)gemm_s<4>,
                         cudaFuncAttributeMaxDynamicSharedMemorySize, SMEM_TOTAL);

    const long PD = (long)MTOT * DIM;     // per-z projection stride
    const int nIn4 = MTOT * DIM / 4;

    // ---- Gather biases (capturable D2D async copies) ----
    cudaMemcpyAsync(bias,           bq, DIM * sizeof(float), cudaMemcpyDeviceToDevice);
    cudaMemcpyAsync(bias + DIM,     bk, DIM * sizeof(float), cudaMemcpyDeviceToDevice);
    cudaMemcpyAsync(bias + 2 * DIM, bv, DIM * sizeof(float), cudaMemcpyDeviceToDevice);

    // ---- Inputs -> fp16; weights -> fp16 transposed ----
    cvt3<<<dim3(nIn4 / 256, 1, 3), 256>>>(query, key, value, x, nIn4);
    wcvtT3<<<dim3(DIM / 32, DIM / 32, 3), dim3(32, 8)>>>(Wq, Wk, Wv, w, DIM, DIM);

    // ---- Batched projections (z=3), fp16 out + bias ----
    gemm_s<2><<<dim3(DIM / 128, MTOT / 128, 3), 256, SMEM_TOTAL>>>(
        x, PD, w, (long)DIM * DIM, bias, DIM, nullptr,
        nullptr, qkv, PD, DIM, DIM);

    // ---- Transpose V to [z][D][S] ----
    vtransT<<<dim3(DIM / 32, SEQ / 32, BATCH), dim3(32, 8)>>>(qkv + 2 * PD, vt);

    // ---- Scores + fused exp: p = exp(beta * q @ k^T), fp16 ----
    gemm_s<3><<<dim3(SEQ / 128, SEQ / 128, BATCH), 256, SMEM_TOTAL>>>(
        qkv, (long)SEQ * DIM, qkv + PD, (long)SEQ * DIM,
        nullptr, 0, nullptr, nullptr, pp, (long)SEQ * SEQ, DIM, SEQ);

    // ---- Row reciprocal sums ----
    rowsum_inv<<<MTOT, 256>>>(pp, rinv);

    // ---- Out: (p @ v^T) * rinv, fp32 ----
    gemm_s<4><<<dim3(DIM / 128, SEQ / 128, BATCH), 256, SMEM_TOTAL>>>(
        pp, (long)SEQ * SEQ, vt, (long)SEQ * DIM,
        nullptr, 0, rinv, out, nullptr, (long)SEQ * DIM, SEQ, DIM);
}